// round 10
// baseline (speedup 1.0000x reference)
#include <cuda_runtime.h>
#include <cuda_bf16.h>
#include <math.h>
#include <stdint.h>

// ---------------------------------------------------------------------------
// Problem constants
// ---------------------------------------------------------------------------
#define B_N 8192
#define D_N 512
#define K_N 20

// GEMM tiling
#define BM 128
#define CK 64                  // K elems per chunk (64 bf16 = 128B row)
#define NC (D_N / CK)          // 8 chunks
#define NBLK (B_N / BM)        // 64
#define NTILE (NBLK * (NBLK + 1) / 2)  // 2080 triangular tiles
#define LDC 129

#define STG_A 16384
#define STG_BUF 32768
#define SMEM_BYTES 66048

#define CAP 768                // candidate buffer per row

// ---------------------------------------------------------------------------
// Scratch (__device__ globals — allocation-free)
// ---------------------------------------------------------------------------
__device__ __align__(128) __nv_bfloat16 g_xb[B_N * D_N];
__device__ __align__(128) float g_cos[(size_t)B_N * B_N];   // 268 MB
__device__ float g_rowloss[B_N];

// ---------------------------------------------------------------------------
// PTX helpers
// ---------------------------------------------------------------------------
__device__ __forceinline__ uint32_t smem_u32(const void* p) {
    uint32_t a;
    asm("{ .reg .u64 t; cvta.to.shared.u64 t, %1; cvt.u32.u64 %0, t; }" : "=r"(a) : "l"(p));
    return a;
}

__device__ __forceinline__ void cp_async16(uint32_t dst, const void* src) {
    asm volatile("cp.async.cg.shared.global [%0], [%1], 16;" :: "r"(dst), "l"(src) : "memory");
}
#define CP_COMMIT() asm volatile("cp.async.commit_group;" ::: "memory")
#define CP_WAIT1()  asm volatile("cp.async.wait_group 1;" ::: "memory")
#define CP_WAIT0()  asm volatile("cp.async.wait_group 0;" ::: "memory")

#define LDSM_X4(r0, r1, r2, r3, addr)                                        \
    asm volatile("ldmatrix.sync.aligned.m8n8.x4.shared.b16 {%0,%1,%2,%3}, [%4];" \
                 : "=r"(r0), "=r"(r1), "=r"(r2), "=r"(r3) : "r"(addr))

__device__ __forceinline__ void mma16816(float* c, uint32_t a0, uint32_t a1,
                                         uint32_t a2, uint32_t a3,
                                         uint32_t b0, uint32_t b1) {
    asm volatile(
        "mma.sync.aligned.m16n8k16.row.col.f32.bf16.bf16.f32 "
        "{%0,%1,%2,%3}, {%4,%5,%6,%7}, {%8,%9}, {%0,%1,%2,%3};"
        : "+f"(c[0]), "+f"(c[1]), "+f"(c[2]), "+f"(c[3])
        : "r"(a0), "r"(a1), "r"(a2), "r"(a3), "r"(b0), "r"(b1));
}

__global__ void dummy_a_kernel() {}

// ---------------------------------------------------------------------------
// 1) Row L2 normalization -> bf16
// ---------------------------------------------------------------------------
__global__ void normalize_kernel(const float* __restrict__ x) {
    __shared__ float warp_ss[4];
    __shared__ float s_inv;
    int row = blockIdx.x;
    int t = threadIdx.x;  // 128
    const float* xr = x + row * D_N;
    float v[4];
    float ss = 0.f;
#pragma unroll
    for (int i = 0; i < 4; i++) { v[i] = xr[t + 128 * i]; ss += v[i] * v[i]; }
#pragma unroll
    for (int off = 16; off > 0; off >>= 1) ss += __shfl_xor_sync(0xffffffffu, ss, off);
    if ((t & 31) == 0) warp_ss[t >> 5] = ss;
    __syncthreads();
    if (t == 0) {
        float tot = warp_ss[0] + warp_ss[1] + warp_ss[2] + warp_ss[3];
        s_inv = 1.0f / fmaxf(sqrtf(tot), 1e-12f);
    }
    __syncthreads();
    float inv = s_inv;
#pragma unroll
    for (int i = 0; i < 4; i++)
        g_xb[row * D_N + t + 128 * i] = __float2bfloat16_rn(v[i] * inv);
}

// ---------------------------------------------------------------------------
// 2) Symmetric bf16 mma.sync GEMM -> g_cos (both mirrors; diagonal := -2)
//    512 threads = 16 warps (4x4), warp tile 32x32, 2-stage cp.async
// ---------------------------------------------------------------------------
extern __shared__ char smem_raw[];

__global__ __launch_bounds__(512, 1) void gemm_sym_kernel() {
    const int tid = threadIdx.x;
    const int lane = tid & 31;
    const int wid = tid >> 5;
    const int wm = wid & 3;
    const int wn = wid >> 2;

    int bi = 0, rem = blockIdx.x;
    while (rem >= NBLK - bi) { rem -= NBLK - bi; bi++; }
    const int bj = bi + rem;
    const int rowBase = bi * BM;
    const int colBase = bj * BM;

    const uint32_t sbase = smem_u32(smem_raw);
    float* Csh = (float*)smem_raw;

    uint32_t soff[2], grow[2];
#pragma unroll
    for (int i = 0; i < 2; i++) {
        int cid = tid + 512 * i;
        int r = cid >> 3, c16 = cid & 7;
        soff[i] = (uint32_t)(r * 128 + ((c16 * 16) ^ ((r & 7) << 4)));
        grow[i] = (uint32_t)(r * (D_N * 2) + c16 * 16);
    }
    const char* Agbase = (const char*)g_xb + (size_t)rowBase * D_N * 2;
    const char* Bgbase = (const char*)g_xb + (size_t)colBase * D_N * 2;

    const uint32_t rx = (uint32_t)((lane & 7) << 4);
    const uint32_t ah = (uint32_t)((lane >> 4) << 4);
    const uint32_t bh = (uint32_t)(((lane >> 3) & 1) << 4);
    const uint32_t arow0 = (uint32_t)((wm * 32 + (lane & 7) + ((lane >> 3) & 1) * 8) * 128);
    const uint32_t brow0 = (uint32_t)((wn * 32 + (lane & 7) + (lane >> 4) * 8) * 128);

    float acc[2][4][4];
#pragma unroll
    for (int mt = 0; mt < 2; mt++)
#pragma unroll
        for (int nt = 0; nt < 4; nt++)
#pragma unroll
            for (int q = 0; q < 4; q++) acc[mt][nt][q] = 0.f;

#pragma unroll
    for (int pc = 0; pc < 2; pc++) {
        uint32_t ab = sbase + pc * STG_BUF;
        const char* Ag = Agbase + pc * (CK * 2);
        const char* Bg = Bgbase + pc * (CK * 2);
#pragma unroll
        for (int i = 0; i < 2; i++) {
            cp_async16(ab + soff[i], Ag + grow[i]);
            cp_async16(ab + STG_A + soff[i], Bg + grow[i]);
        }
        CP_COMMIT();
    }

#pragma unroll
    for (int kc = 0; kc < NC; kc++) {
        if (kc == NC - 1) CP_WAIT0(); else CP_WAIT1();
        __syncthreads();

        const uint32_t ab = sbase + (kc & 1) * STG_BUF;
        const uint32_t bb = ab + STG_A;
#pragma unroll
        for (int ks = 0; ks < 4; ks++) {
            const uint32_t kbyte = (uint32_t)(ks * 32);
            uint32_t a[2][4], b[2][4];
#pragma unroll
            for (int mt = 0; mt < 2; mt++)
                LDSM_X4(a[mt][0], a[mt][1], a[mt][2], a[mt][3],
                        ab + arow0 + mt * 2048 + ((kbyte + ah) ^ rx));
#pragma unroll
            for (int np = 0; np < 2; np++)
                LDSM_X4(b[np][0], b[np][1], b[np][2], b[np][3],
                        bb + brow0 + np * 2048 + ((kbyte + bh) ^ rx));
#pragma unroll
            for (int mt = 0; mt < 2; mt++)
#pragma unroll
                for (int nt = 0; nt < 4; nt++)
                    mma16816(acc[mt][nt],
                             a[mt][0], a[mt][1], a[mt][2], a[mt][3],
                             b[nt >> 1][2 * (nt & 1)], b[nt >> 1][2 * (nt & 1) + 1]);
        }
        __syncthreads();

        if (kc + 2 < NC) {
            uint32_t ab2 = sbase + (kc & 1) * STG_BUF;
            const char* Ag = Agbase + (kc + 2) * (CK * 2);
            const char* Bg = Bgbase + (kc + 2) * (CK * 2);
#pragma unroll
            for (int i = 0; i < 2; i++) {
                cp_async16(ab2 + soff[i], Ag + grow[i]);
                cp_async16(ab2 + STG_A + soff[i], Bg + grow[i]);
            }
            CP_COMMIT();
        }
    }

    // dump accumulators to Csh
    {
        const int g = lane >> 2;
        const int c2 = 2 * (lane & 3);
#pragma unroll
        for (int mt = 0; mt < 2; mt++) {
            const int r0 = wm * 32 + mt * 16 + g;
#pragma unroll
            for (int nt = 0; nt < 4; nt++) {
                const int c0 = wn * 32 + nt * 8 + c2;
                Csh[r0 * LDC + c0]           = acc[mt][nt][0];
                Csh[r0 * LDC + c0 + 1]       = acc[mt][nt][1];
                Csh[(r0 + 8) * LDC + c0]     = acc[mt][nt][2];
                Csh[(r0 + 8) * LDC + c0 + 1] = acc[mt][nt][3];
            }
        }
    }
    __syncthreads();

    // direct store (diagonal tiles: overwrite c==r with -2 sentinel)
#pragma unroll
    for (int i = 0; i < 8; i++) {
        int p = tid + 512 * i;
        int r = p >> 5;
        int c4 = (p & 31) * 4;
        float4 o;
        o.x = Csh[r * LDC + c4];
        o.y = Csh[r * LDC + c4 + 1];
        o.z = Csh[r * LDC + c4 + 2];
        o.w = Csh[r * LDC + c4 + 3];
        if (bi == bj) {
            int d = r - c4;
            if (d >= 0 && d < 4) ((float*)&o)[d] = -2.0f;
        }
        *(float4*)(g_cos + (size_t)(rowBase + r) * B_N + colBase + c4) = o;
    }

    // mirror store for off-diagonal tiles
    if (bi != bj) {
#pragma unroll
        for (int i = 0; i < 8; i++) {
            int p = tid + 512 * i;
            int c = p >> 5;
            int r4 = (p & 31) * 4;
            float4 o;
            o.x = Csh[(r4 + 0) * LDC + c];
            o.y = Csh[(r4 + 1) * LDC + c];
            o.z = Csh[(r4 + 2) * LDC + c];
            o.w = Csh[(r4 + 3) * LDC + c];
            *(float4*)(g_cos + (size_t)(colBase + c) * B_N + rowBase + r4) = o;
        }
    }
}

// ---------------------------------------------------------------------------
// 3) Per-row exact top-20: single-pass, register-resident, ballot-free
// ---------------------------------------------------------------------------
__global__ __launch_bounds__(256) void topk_loss_kernel(const int* __restrict__ labels) {
    __shared__ float s_max[256];
    __shared__ float s_cv[CAP];
    __shared__ int   s_ci[CAP];
    __shared__ int   s_cnt;
    __shared__ float s_t;

    const int row = blockIdx.x;
    const int tid = threadIdx.x;
    const float4* rp = (const float4*)(g_cos + (size_t)row * B_N);

    // Phase 1: load entire row slice into registers, per-thread max (branchless)
    float4 rv[8];
    float mx = -3.0f;
#pragma unroll
    for (int i = 0; i < 8; i++) {
        rv[i] = rp[tid + 256 * i];
        mx = fmaxf(mx, fmaxf(fmaxf(rv[i].x, rv[i].y), fmaxf(rv[i].z, rv[i].w)));
    }
    s_max[tid] = mx;
    if (tid == 0) s_cnt = 0;
    __syncthreads();

    // Phase 1.5: warp 0 computes the 20th-largest of the 256 thread maxes.
    // Guarantee: the 20 largest thread-maxes are 20 distinct elements >= t.
    if (tid < 32) {
        float m[8];
#pragma unroll
        for (int i = 0; i < 8; i++) m[i] = s_max[tid + 32 * i];
        float tlast = -3.0f;
        for (int rd = 0; rd < K_N; rd++) {
            float bv = m[0]; int bq = 0;
#pragma unroll
            for (int q = 1; q < 8; q++) if (m[q] > bv) { bv = m[q]; bq = q; }
            float v = bv; int li = tid;
#pragma unroll
            for (int s = 16; s > 0; s >>= 1) {
                float ov = __shfl_xor_sync(0xffffffffu, v, s);
                int   ol = __shfl_xor_sync(0xffffffffu, li, s);
                if (ov > v || (ov == v && ol < li)) { v = ov; li = ol; }
            }
            if (li == tid) {
#pragma unroll
                for (int q = 0; q < 8; q++) if (q == bq) m[q] = -3.0f;
            }
            tlast = v;
        }
        if (tid == 0) s_t = tlast;
    }
    __syncthreads();

    // Phase 2: only threads whose max >= t rescan their REGISTERS (few threads)
    const float t = s_t;
    if (mx >= t) {
#pragma unroll
        for (int i = 0; i < 8; i++) {
            float vv[4] = {rv[i].x, rv[i].y, rv[i].z, rv[i].w};
            int c0 = (tid + 256 * i) * 4;
#pragma unroll
            for (int j = 0; j < 4; j++) {
                if (vv[j] >= t) {
                    int p = atomicAdd(&s_cnt, 1);
                    if (p < CAP) { s_cv[p] = vv[j]; s_ci[p] = c0 + j; }
                }
            }
        }
    }
    __syncthreads();

    // Phase 3: warp 0 — 20 exact argmax rounds over candidates + BCE
    if (tid < 32) {
        int nc = s_cnt; if (nc > CAP) nc = CAP;
        const int lab = labels[row];
        float rloss = 0.f;
        for (int rd = 0; rd < K_N; rd++) {
            float bv = -3.0f; int bp = -1;
            for (int p = tid; p < nc; p += 32) {
                float v = s_cv[p];
                if (v > bv) { bv = v; bp = p; }
            }
            float v = bv; int pi = bp;
#pragma unroll
            for (int s = 16; s > 0; s >>= 1) {
                float ov = __shfl_xor_sync(0xffffffffu, v, s);
                int   op = __shfl_xor_sync(0xffffffffu, pi, s);
                if (ov > v || (ov == v && op >= 0 && (pi < 0 || op < pi))) { v = ov; pi = op; }
            }
            if (tid == 0) {
                int col = s_ci[pi];
                float pred = 0.5f * (v + 1.0f);
                float lp = fmaxf(logf(pred), -100.0f);
                float l1 = fmaxf(log1pf(-pred), -100.0f);
                rloss += (labels[col] == lab) ? -lp : -l1;
                s_cv[pi] = -3.0f;
            }
            __syncwarp();
        }
        if (tid == 0) g_rowloss[row] = rloss;
    }
}

// ---------------------------------------------------------------------------
// 4) Deterministic final reduction over 8192 row losses
// ---------------------------------------------------------------------------
__global__ void reduce_kernel(float* __restrict__ out) {
    __shared__ double sh[256];
    int t = threadIdx.x;
    double s = 0.0;
    for (int i = t; i < B_N; i += 256) s += (double)g_rowloss[i];
    sh[t] = s;
    __syncthreads();
    for (int off = 128; off > 0; off >>= 1) {
        if (t < off) sh[t] += sh[t + off];
        __syncthreads();
    }
    if (t == 0) out[0] = (float)(sh[0] / (double)((long long)B_N * K_N));
}

// ---------------------------------------------------------------------------
extern "C" void kernel_launch(void* const* d_in, const int* in_sizes, int n_in,
                              void* d_out, int out_size) {
    const float* batch  = (const float*)d_in[0];
    const int*   labels = (const int*)d_in[1];
    float* out = (float*)d_out;
    (void)in_sizes; (void)n_in; (void)out_size;

    cudaFuncSetAttribute(gemm_sym_kernel, cudaFuncAttributeMaxDynamicSharedMemorySize,
                         SMEM_BYTES);

    normalize_kernel<<<B_N, 128>>>(batch);             // launch 1
    gemm_sym_kernel<<<NTILE, 512, SMEM_BYTES>>>();     // launch 2
    dummy_a_kernel<<<1, 32>>>();                       // launch 3 (slot shim)
    topk_loss_kernel<<<B_N, 256>>>(labels);            // launch 4 -> ncu slot
    reduce_kernel<<<1, 256>>>(out);                    // launch 5
}

// round 11
// speedup vs baseline: 1.2814x; 1.2814x over previous
#include <cuda_runtime.h>
#include <cuda_bf16.h>
#include <math.h>
#include <stdint.h>

// ---------------------------------------------------------------------------
// Problem constants
// ---------------------------------------------------------------------------
#define B_N 8192
#define D_N 512
#define K_N 20

// GEMM tiling
#define BM 128
#define CK 64                  // K elems per chunk (64 bf16 = 128B row)
#define NC (D_N / CK)          // 8 chunks
#define NBLK (B_N / BM)        // 64
#define NTILE (NBLK * (NBLK + 1) / 2)  // 2080 triangular tiles
#define LDC 129

#define STG_A 16384
#define STG_BUF 32768
#define SMEM_BYTES 66048

#define CAP 768                // candidate buffer per row

// ---------------------------------------------------------------------------
// Scratch (__device__ globals — allocation-free)
// ---------------------------------------------------------------------------
__device__ __align__(128) __nv_bfloat16 g_xb[B_N * D_N];
__device__ __align__(128) float g_cos[(size_t)B_N * B_N];   // 268 MB
__device__ float g_rowloss[B_N];

// ---------------------------------------------------------------------------
// PTX helpers
// ---------------------------------------------------------------------------
__device__ __forceinline__ uint32_t smem_u32(const void* p) {
    uint32_t a;
    asm("{ .reg .u64 t; cvta.to.shared.u64 t, %1; cvt.u32.u64 %0, t; }" : "=r"(a) : "l"(p));
    return a;
}

__device__ __forceinline__ void cp_async16(uint32_t dst, const void* src) {
    asm volatile("cp.async.cg.shared.global [%0], [%1], 16;" :: "r"(dst), "l"(src) : "memory");
}
#define CP_COMMIT() asm volatile("cp.async.commit_group;" ::: "memory")
#define CP_WAIT1()  asm volatile("cp.async.wait_group 1;" ::: "memory")
#define CP_WAIT0()  asm volatile("cp.async.wait_group 0;" ::: "memory")

#define LDSM_X4(r0, r1, r2, r3, addr)                                        \
    asm volatile("ldmatrix.sync.aligned.m8n8.x4.shared.b16 {%0,%1,%2,%3}, [%4];" \
                 : "=r"(r0), "=r"(r1), "=r"(r2), "=r"(r3) : "r"(addr))

__device__ __forceinline__ void mma16816(float* c, uint32_t a0, uint32_t a1,
                                         uint32_t a2, uint32_t a3,
                                         uint32_t b0, uint32_t b1) {
    asm volatile(
        "mma.sync.aligned.m16n8k16.row.col.f32.bf16.bf16.f32 "
        "{%0,%1,%2,%3}, {%4,%5,%6,%7}, {%8,%9}, {%0,%1,%2,%3};"
        : "+f"(c[0]), "+f"(c[1]), "+f"(c[2]), "+f"(c[3])
        : "r"(a0), "r"(a1), "r"(a2), "r"(a3), "r"(b0), "r"(b1));
}

__global__ void dummy_a_kernel() {}

// ---------------------------------------------------------------------------
// 1) Row L2 normalization -> bf16
// ---------------------------------------------------------------------------
__global__ void normalize_kernel(const float* __restrict__ x) {
    __shared__ float warp_ss[4];
    __shared__ float s_inv;
    int row = blockIdx.x;
    int t = threadIdx.x;  // 128
    const float* xr = x + row * D_N;
    float v[4];
    float ss = 0.f;
#pragma unroll
    for (int i = 0; i < 4; i++) { v[i] = xr[t + 128 * i]; ss += v[i] * v[i]; }
#pragma unroll
    for (int off = 16; off > 0; off >>= 1) ss += __shfl_xor_sync(0xffffffffu, ss, off);
    if ((t & 31) == 0) warp_ss[t >> 5] = ss;
    __syncthreads();
    if (t == 0) {
        float tot = warp_ss[0] + warp_ss[1] + warp_ss[2] + warp_ss[3];
        s_inv = 1.0f / fmaxf(sqrtf(tot), 1e-12f);
    }
    __syncthreads();
    float inv = s_inv;
#pragma unroll
    for (int i = 0; i < 4; i++)
        g_xb[row * D_N + t + 128 * i] = __float2bfloat16_rn(v[i] * inv);
}

// ---------------------------------------------------------------------------
// 2) Symmetric bf16 mma.sync GEMM -> g_cos (both mirrors; diagonal := -2)
//    512 threads = 16 warps (4x4), warp tile 32x32, 2-stage cp.async
// ---------------------------------------------------------------------------
extern __shared__ char smem_raw[];

__global__ __launch_bounds__(512, 1) void gemm_sym_kernel() {
    const int tid = threadIdx.x;
    const int lane = tid & 31;
    const int wid = tid >> 5;
    const int wm = wid & 3;
    const int wn = wid >> 2;

    int bi = 0, rem = blockIdx.x;
    while (rem >= NBLK - bi) { rem -= NBLK - bi; bi++; }
    const int bj = bi + rem;
    const int rowBase = bi * BM;
    const int colBase = bj * BM;

    const uint32_t sbase = smem_u32(smem_raw);
    float* Csh = (float*)smem_raw;

    uint32_t soff[2], grow[2];
#pragma unroll
    for (int i = 0; i < 2; i++) {
        int cid = tid + 512 * i;
        int r = cid >> 3, c16 = cid & 7;
        soff[i] = (uint32_t)(r * 128 + ((c16 * 16) ^ ((r & 7) << 4)));
        grow[i] = (uint32_t)(r * (D_N * 2) + c16 * 16);
    }
    const char* Agbase = (const char*)g_xb + (size_t)rowBase * D_N * 2;
    const char* Bgbase = (const char*)g_xb + (size_t)colBase * D_N * 2;

    const uint32_t rx = (uint32_t)((lane & 7) << 4);
    const uint32_t ah = (uint32_t)((lane >> 4) << 4);
    const uint32_t bh = (uint32_t)(((lane >> 3) & 1) << 4);
    const uint32_t arow0 = (uint32_t)((wm * 32 + (lane & 7) + ((lane >> 3) & 1) * 8) * 128);
    const uint32_t brow0 = (uint32_t)((wn * 32 + (lane & 7) + (lane >> 4) * 8) * 128);

    float acc[2][4][4];
#pragma unroll
    for (int mt = 0; mt < 2; mt++)
#pragma unroll
        for (int nt = 0; nt < 4; nt++)
#pragma unroll
            for (int q = 0; q < 4; q++) acc[mt][nt][q] = 0.f;

#pragma unroll
    for (int pc = 0; pc < 2; pc++) {
        uint32_t ab = sbase + pc * STG_BUF;
        const char* Ag = Agbase + pc * (CK * 2);
        const char* Bg = Bgbase + pc * (CK * 2);
#pragma unroll
        for (int i = 0; i < 2; i++) {
            cp_async16(ab + soff[i], Ag + grow[i]);
            cp_async16(ab + STG_A + soff[i], Bg + grow[i]);
        }
        CP_COMMIT();
    }

#pragma unroll
    for (int kc = 0; kc < NC; kc++) {
        if (kc == NC - 1) CP_WAIT0(); else CP_WAIT1();
        __syncthreads();

        const uint32_t ab = sbase + (kc & 1) * STG_BUF;
        const uint32_t bb = ab + STG_A;
#pragma unroll
        for (int ks = 0; ks < 4; ks++) {
            const uint32_t kbyte = (uint32_t)(ks * 32);
            uint32_t a[2][4], b[2][4];
#pragma unroll
            for (int mt = 0; mt < 2; mt++)
                LDSM_X4(a[mt][0], a[mt][1], a[mt][2], a[mt][3],
                        ab + arow0 + mt * 2048 + ((kbyte + ah) ^ rx));
#pragma unroll
            for (int np = 0; np < 2; np++)
                LDSM_X4(b[np][0], b[np][1], b[np][2], b[np][3],
                        bb + brow0 + np * 2048 + ((kbyte + bh) ^ rx));
#pragma unroll
            for (int mt = 0; mt < 2; mt++)
#pragma unroll
                for (int nt = 0; nt < 4; nt++)
                    mma16816(acc[mt][nt],
                             a[mt][0], a[mt][1], a[mt][2], a[mt][3],
                             b[nt >> 1][2 * (nt & 1)], b[nt >> 1][2 * (nt & 1) + 1]);
        }
        __syncthreads();

        if (kc + 2 < NC) {
            uint32_t ab2 = sbase + (kc & 1) * STG_BUF;
            const char* Ag = Agbase + (kc + 2) * (CK * 2);
            const char* Bg = Bgbase + (kc + 2) * (CK * 2);
#pragma unroll
            for (int i = 0; i < 2; i++) {
                cp_async16(ab2 + soff[i], Ag + grow[i]);
                cp_async16(ab2 + STG_A + soff[i], Bg + grow[i]);
            }
            CP_COMMIT();
        }
    }

    // dump accumulators to Csh
    {
        const int g = lane >> 2;
        const int c2 = 2 * (lane & 3);
#pragma unroll
        for (int mt = 0; mt < 2; mt++) {
            const int r0 = wm * 32 + mt * 16 + g;
#pragma unroll
            for (int nt = 0; nt < 4; nt++) {
                const int c0 = wn * 32 + nt * 8 + c2;
                Csh[r0 * LDC + c0]           = acc[mt][nt][0];
                Csh[r0 * LDC + c0 + 1]       = acc[mt][nt][1];
                Csh[(r0 + 8) * LDC + c0]     = acc[mt][nt][2];
                Csh[(r0 + 8) * LDC + c0 + 1] = acc[mt][nt][3];
            }
        }
    }
    __syncthreads();

    // direct store (diagonal tiles: overwrite c==r with -2 sentinel)
#pragma unroll
    for (int i = 0; i < 8; i++) {
        int p = tid + 512 * i;
        int r = p >> 5;
        int c4 = (p & 31) * 4;
        float4 o;
        o.x = Csh[r * LDC + c4];
        o.y = Csh[r * LDC + c4 + 1];
        o.z = Csh[r * LDC + c4 + 2];
        o.w = Csh[r * LDC + c4 + 3];
        if (bi == bj) {
            int d = r - c4;
            if (d >= 0 && d < 4) ((float*)&o)[d] = -2.0f;
        }
        *(float4*)(g_cos + (size_t)(rowBase + r) * B_N + colBase + c4) = o;
    }

    // mirror store for off-diagonal tiles
    if (bi != bj) {
#pragma unroll
        for (int i = 0; i < 8; i++) {
            int p = tid + 512 * i;
            int c = p >> 5;
            int r4 = (p & 31) * 4;
            float4 o;
            o.x = Csh[(r4 + 0) * LDC + c];
            o.y = Csh[(r4 + 1) * LDC + c];
            o.z = Csh[(r4 + 2) * LDC + c];
            o.w = Csh[(r4 + 3) * LDC + c];
            *(float4*)(g_cos + (size_t)(colBase + c) * B_N + rowBase + r4) = o;
        }
    }
}

// ---------------------------------------------------------------------------
// 3) Per-row exact top-20: streaming max pass + max-gated sparse re-read
// ---------------------------------------------------------------------------
__global__ __launch_bounds__(256) void topk_loss_kernel(const int* __restrict__ labels) {
    __shared__ float s_max[256];
    __shared__ float s_cv[CAP];
    __shared__ int   s_ci[CAP];
    __shared__ int   s_cnt;
    __shared__ float s_t;

    const int row = blockIdx.x;
    const int tid = threadIdx.x;
    const float4* rp = (const float4*)(g_cos + (size_t)row * B_N);

    // Phase 1: streaming per-thread max over 32 elems (no register retention)
    float mx = -3.0f;
#pragma unroll
    for (int i = 0; i < 8; i++) {
        float4 v = rp[tid + 256 * i];
        mx = fmaxf(mx, fmaxf(fmaxf(v.x, v.y), fmaxf(v.z, v.w)));
    }
    s_max[tid] = mx;
    if (tid == 0) s_cnt = 0;
    __syncthreads();

    // Phase 1.5: warp 0 computes the 20th-largest of the 256 thread maxes.
    // Guarantee: the 20 largest thread-maxes are 20 distinct elements >= t.
    if (tid < 32) {
        float m[8];
#pragma unroll
        for (int i = 0; i < 8; i++) m[i] = s_max[tid + 32 * i];
        float tlast = -3.0f;
        for (int rd = 0; rd < K_N; rd++) {
            float bv = m[0]; int bq = 0;
#pragma unroll
            for (int q = 1; q < 8; q++) if (m[q] > bv) { bv = m[q]; bq = q; }
            float v = bv; int li = tid;
#pragma unroll
            for (int s = 16; s > 0; s >>= 1) {
                float ov = __shfl_xor_sync(0xffffffffu, v, s);
                int   ol = __shfl_xor_sync(0xffffffffu, li, s);
                if (ov > v || (ov == v && ol < li)) { v = ov; li = ol; }
            }
            if (li == tid) {
#pragma unroll
                for (int q = 0; q < 8; q++) if (q == bq) m[q] = -3.0f;
            }
            tlast = v;
        }
        if (tid == 0) s_t = tlast;
    }
    __syncthreads();

    // Phase 2: only threads with mx >= t (<= 20 per block) re-read their 32
    // elements (L2-hot) and push candidates via rare shared atomics.
    const float t = s_t;
    if (mx >= t) {
#pragma unroll
        for (int i = 0; i < 8; i++) {
            float4 v4 = rp[tid + 256 * i];
            int c0 = (tid + 256 * i) * 4;
            float vv[4] = {v4.x, v4.y, v4.z, v4.w};
#pragma unroll
            for (int j = 0; j < 4; j++) {
                if (vv[j] >= t) {
                    int p = atomicAdd(&s_cnt, 1);
                    if (p < CAP) { s_cv[p] = vv[j]; s_ci[p] = c0 + j; }
                }
            }
        }
    }
    __syncthreads();

    // Phase 3: warp 0 — 20 exact argmax rounds over candidates + BCE
    if (tid < 32) {
        int nc = s_cnt; if (nc > CAP) nc = CAP;
        const int lab = labels[row];
        float rloss = 0.f;
        for (int rd = 0; rd < K_N; rd++) {
            float bv = -3.0f; int bp = -1;
            for (int p = tid; p < nc; p += 32) {
                float v = s_cv[p];
                if (v > bv) { bv = v; bp = p; }
            }
            float v = bv; int pi = bp;
#pragma unroll
            for (int s = 16; s > 0; s >>= 1) {
                float ov = __shfl_xor_sync(0xffffffffu, v, s);
                int   op = __shfl_xor_sync(0xffffffffu, pi, s);
                if (ov > v || (ov == v && op >= 0 && (pi < 0 || op < pi))) { v = ov; pi = op; }
            }
            if (tid == 0) {
                int col = s_ci[pi];
                float pred = 0.5f * (v + 1.0f);
                float lp = fmaxf(logf(pred), -100.0f);
                float l1 = fmaxf(log1pf(-pred), -100.0f);
                rloss += (labels[col] == lab) ? -lp : -l1;
                s_cv[pi] = -3.0f;
            }
            __syncwarp();
        }
        if (tid == 0) g_rowloss[row] = rloss;
    }
}

// ---------------------------------------------------------------------------
// 4) Deterministic final reduction over 8192 row losses
// ---------------------------------------------------------------------------
__global__ void reduce_kernel(float* __restrict__ out) {
    __shared__ double sh[256];
    int t = threadIdx.x;
    double s = 0.0;
    for (int i = t; i < B_N; i += 256) s += (double)g_rowloss[i];
    sh[t] = s;
    __syncthreads();
    for (int off = 128; off > 0; off >>= 1) {
        if (t < off) sh[t] += sh[t + off];
        __syncthreads();
    }
    if (t == 0) out[0] = (float)(sh[0] / (double)((long long)B_N * K_N));
}

// ---------------------------------------------------------------------------
extern "C" void kernel_launch(void* const* d_in, const int* in_sizes, int n_in,
                              void* d_out, int out_size) {
    const float* batch  = (const float*)d_in[0];
    const int*   labels = (const int*)d_in[1];
    float* out = (float*)d_out;
    (void)in_sizes; (void)n_in; (void)out_size;

    cudaFuncSetAttribute(gemm_sym_kernel, cudaFuncAttributeMaxDynamicSharedMemorySize,
                         SMEM_BYTES);

    normalize_kernel<<<B_N, 128>>>(batch);             // launch 1
    gemm_sym_kernel<<<NTILE, 512, SMEM_BYTES>>>();     // launch 2
    dummy_a_kernel<<<1, 32>>>();                       // launch 3 (slot shim)
    topk_loss_kernel<<<B_N, 256>>>(labels);            // launch 4 -> ncu slot
    reduce_kernel<<<1, 256>>>(out);                    // launch 5
}

// round 12
// speedup vs baseline: 1.2935x; 1.0094x over previous
#include <cuda_runtime.h>
#include <cuda_bf16.h>
#include <math.h>
#include <stdint.h>

// ---------------------------------------------------------------------------
// Problem constants
// ---------------------------------------------------------------------------
#define B_N 8192
#define D_N 512
#define K_N 20
#define NSEGS (B_N / 32)       // 256 column segments of 32

// GEMM tiling
#define BM 128
#define CK 64                  // K elems per chunk (64 bf16 = 128B row)
#define NC (D_N / CK)          // 8 chunks
#define NBLK (B_N / BM)        // 64
#define NTILE (NBLK * (NBLK + 1) / 2)  // 2080 triangular tiles
#define LDC 129

#define STG_A 16384
#define STG_BUF 32768
#define SMEM_BYTES 66048

#define CAP 768                // candidate buffer per row

// ---------------------------------------------------------------------------
// Scratch (__device__ globals — allocation-free)
// ---------------------------------------------------------------------------
__device__ __align__(128) __nv_bfloat16 g_xb[B_N * D_N];
__device__ __align__(128) float g_cos[(size_t)B_N * B_N];   // 268 MB
__device__ __align__(128) float g_mx[(size_t)B_N * NSEGS];  // 8 MB segment maxes
__device__ float g_rowloss[B_N];

// ---------------------------------------------------------------------------
// PTX helpers
// ---------------------------------------------------------------------------
__device__ __forceinline__ uint32_t smem_u32(const void* p) {
    uint32_t a;
    asm("{ .reg .u64 t; cvta.to.shared.u64 t, %1; cvt.u32.u64 %0, t; }" : "=r"(a) : "l"(p));
    return a;
}

__device__ __forceinline__ void cp_async16(uint32_t dst, const void* src) {
    asm volatile("cp.async.cg.shared.global [%0], [%1], 16;" :: "r"(dst), "l"(src) : "memory");
}
#define CP_COMMIT() asm volatile("cp.async.commit_group;" ::: "memory")
#define CP_WAIT1()  asm volatile("cp.async.wait_group 1;" ::: "memory")
#define CP_WAIT0()  asm volatile("cp.async.wait_group 0;" ::: "memory")

#define LDSM_X4(r0, r1, r2, r3, addr)                                        \
    asm volatile("ldmatrix.sync.aligned.m8n8.x4.shared.b16 {%0,%1,%2,%3}, [%4];" \
                 : "=r"(r0), "=r"(r1), "=r"(r2), "=r"(r3) : "r"(addr))

__device__ __forceinline__ void mma16816(float* c, uint32_t a0, uint32_t a1,
                                         uint32_t a2, uint32_t a3,
                                         uint32_t b0, uint32_t b1) {
    asm volatile(
        "mma.sync.aligned.m16n8k16.row.col.f32.bf16.bf16.f32 "
        "{%0,%1,%2,%3}, {%4,%5,%6,%7}, {%8,%9}, {%0,%1,%2,%3};"
        : "+f"(c[0]), "+f"(c[1]), "+f"(c[2]), "+f"(c[3])
        : "r"(a0), "r"(a1), "r"(a2), "r"(a3), "r"(b0), "r"(b1));
}

__global__ void dummy_a_kernel() {}
__global__ void dummy_b_kernel() {}

// ---------------------------------------------------------------------------
// 1) Row L2 normalization -> bf16
// ---------------------------------------------------------------------------
__global__ void normalize_kernel(const float* __restrict__ x) {
    __shared__ float warp_ss[4];
    __shared__ float s_inv;
    int row = blockIdx.x;
    int t = threadIdx.x;  // 128
    const float* xr = x + row * D_N;
    float v[4];
    float ss = 0.f;
#pragma unroll
    for (int i = 0; i < 4; i++) { v[i] = xr[t + 128 * i]; ss += v[i] * v[i]; }
#pragma unroll
    for (int off = 16; off > 0; off >>= 1) ss += __shfl_xor_sync(0xffffffffu, ss, off);
    if ((t & 31) == 0) warp_ss[t >> 5] = ss;
    __syncthreads();
    if (t == 0) {
        float tot = warp_ss[0] + warp_ss[1] + warp_ss[2] + warp_ss[3];
        s_inv = 1.0f / fmaxf(sqrtf(tot), 1e-12f);
    }
    __syncthreads();
    float inv = s_inv;
#pragma unroll
    for (int i = 0; i < 4; i++)
        g_xb[row * D_N + t + 128 * i] = __float2bfloat16_rn(v[i] * inv);
}

// ---------------------------------------------------------------------------
// 2) Symmetric bf16 mma.sync GEMM -> g_cos + per-32col segment maxes g_mx
//    512 threads = 16 warps (4x4), warp tile 32x32, 2-stage cp.async
// ---------------------------------------------------------------------------
extern __shared__ char smem_raw[];

__global__ __launch_bounds__(512, 1) void gemm_sym_kernel() {
    const int tid = threadIdx.x;
    const int lane = tid & 31;
    const int wid = tid >> 5;
    const int wm = wid & 3;
    const int wn = wid >> 2;

    int bi = 0, rem = blockIdx.x;
    while (rem >= NBLK - bi) { rem -= NBLK - bi; bi++; }
    const int bj = bi + rem;
    const int rowBase = bi * BM;
    const int colBase = bj * BM;

    const uint32_t sbase = smem_u32(smem_raw);
    float* Csh = (float*)smem_raw;

    uint32_t soff[2], grow[2];
#pragma unroll
    for (int i = 0; i < 2; i++) {
        int cid = tid + 512 * i;
        int r = cid >> 3, c16 = cid & 7;
        soff[i] = (uint32_t)(r * 128 + ((c16 * 16) ^ ((r & 7) << 4)));
        grow[i] = (uint32_t)(r * (D_N * 2) + c16 * 16);
    }
    const char* Agbase = (const char*)g_xb + (size_t)rowBase * D_N * 2;
    const char* Bgbase = (const char*)g_xb + (size_t)colBase * D_N * 2;

    const uint32_t rx = (uint32_t)((lane & 7) << 4);
    const uint32_t ah = (uint32_t)((lane >> 4) << 4);
    const uint32_t bh = (uint32_t)(((lane >> 3) & 1) << 4);
    const uint32_t arow0 = (uint32_t)((wm * 32 + (lane & 7) + ((lane >> 3) & 1) * 8) * 128);
    const uint32_t brow0 = (uint32_t)((wn * 32 + (lane & 7) + (lane >> 4) * 8) * 128);

    float acc[2][4][4];
#pragma unroll
    for (int mt = 0; mt < 2; mt++)
#pragma unroll
        for (int nt = 0; nt < 4; nt++)
#pragma unroll
            for (int q = 0; q < 4; q++) acc[mt][nt][q] = 0.f;

#pragma unroll
    for (int pc = 0; pc < 2; pc++) {
        uint32_t ab = sbase + pc * STG_BUF;
        const char* Ag = Agbase + pc * (CK * 2);
        const char* Bg = Bgbase + pc * (CK * 2);
#pragma unroll
        for (int i = 0; i < 2; i++) {
            cp_async16(ab + soff[i], Ag + grow[i]);
            cp_async16(ab + STG_A + soff[i], Bg + grow[i]);
        }
        CP_COMMIT();
    }

#pragma unroll
    for (int kc = 0; kc < NC; kc++) {
        if (kc == NC - 1) CP_WAIT0(); else CP_WAIT1();
        __syncthreads();

        const uint32_t ab = sbase + (kc & 1) * STG_BUF;
        const uint32_t bb = ab + STG_A;
#pragma unroll
        for (int ks = 0; ks < 4; ks++) {
            const uint32_t kbyte = (uint32_t)(ks * 32);
            uint32_t a[2][4], b[2][4];
#pragma unroll
            for (int mt = 0; mt < 2; mt++)
                LDSM_X4(a[mt][0], a[mt][1], a[mt][2], a[mt][3],
                        ab + arow0 + mt * 2048 + ((kbyte + ah) ^ rx));
#pragma unroll
            for (int np = 0; np < 2; np++)
                LDSM_X4(b[np][0], b[np][1], b[np][2], b[np][3],
                        bb + brow0 + np * 2048 + ((kbyte + bh) ^ rx));
#pragma unroll
            for (int mt = 0; mt < 2; mt++)
#pragma unroll
                for (int nt = 0; nt < 4; nt++)
                    mma16816(acc[mt][nt],
                             a[mt][0], a[mt][1], a[mt][2], a[mt][3],
                             b[nt >> 1][2 * (nt & 1)], b[nt >> 1][2 * (nt & 1) + 1]);
        }
        __syncthreads();

        if (kc + 2 < NC) {
            uint32_t ab2 = sbase + (kc & 1) * STG_BUF;
            const char* Ag = Agbase + (kc + 2) * (CK * 2);
            const char* Bg = Bgbase + (kc + 2) * (CK * 2);
#pragma unroll
            for (int i = 0; i < 2; i++) {
                cp_async16(ab2 + soff[i], Ag + grow[i]);
                cp_async16(ab2 + STG_A + soff[i], Bg + grow[i]);
            }
            CP_COMMIT();
        }
    }

    // dump accumulators to Csh
    {
        const int g = lane >> 2;
        const int c2 = 2 * (lane & 3);
#pragma unroll
        for (int mt = 0; mt < 2; mt++) {
            const int r0 = wm * 32 + mt * 16 + g;
#pragma unroll
            for (int nt = 0; nt < 4; nt++) {
                const int c0 = wn * 32 + nt * 8 + c2;
                Csh[r0 * LDC + c0]           = acc[mt][nt][0];
                Csh[r0 * LDC + c0 + 1]       = acc[mt][nt][1];
                Csh[(r0 + 8) * LDC + c0]     = acc[mt][nt][2];
                Csh[(r0 + 8) * LDC + c0 + 1] = acc[mt][nt][3];
            }
        }
    }
    __syncthreads();

    // diagonal sentinel directly in Csh (so stores AND maxes see it)
    if (bi == bj && tid < BM) Csh[tid * LDC + tid] = -2.0f;
    __syncthreads();

    // direct store
#pragma unroll
    for (int i = 0; i < 8; i++) {
        int p = tid + 512 * i;
        int r = p >> 5;
        int c4 = (p & 31) * 4;
        float4 o;
        o.x = Csh[r * LDC + c4];
        o.y = Csh[r * LDC + c4 + 1];
        o.z = Csh[r * LDC + c4 + 2];
        o.w = Csh[r * LDC + c4 + 3];
        *(float4*)(g_cos + (size_t)(rowBase + r) * B_N + colBase + c4) = o;
    }

    // mirror store for off-diagonal tiles
    if (bi != bj) {
#pragma unroll
        for (int i = 0; i < 8; i++) {
            int p = tid + 512 * i;
            int c = p >> 5;
            int r4 = (p & 31) * 4;
            float4 o;
            o.x = Csh[(r4 + 0) * LDC + c];
            o.y = Csh[(r4 + 1) * LDC + c];
            o.z = Csh[(r4 + 2) * LDC + c];
            o.w = Csh[(r4 + 3) * LDC + c];
            *(float4*)(g_cos + (size_t)(colBase + c) * B_N + rowBase + r4) = o;
        }
    }

    // 32-col segment maxes: direct rows (and mirror columns)
    {
        const int r = tid >> 2;          // 0..127
        const int s = tid & 3;           // 0..3
        const float* base = Csh + r * LDC + s * 32;
        float m = base[0];
#pragma unroll
        for (int c = 1; c < 32; c++) m = fmaxf(m, base[c]);
        g_mx[(size_t)(rowBase + r) * NSEGS + (colBase >> 5) + s] = m;

        if (bi != bj) {
            float m2 = Csh[(s * 32) * LDC + r];
#pragma unroll
            for (int i = 1; i < 32; i++) m2 = fmaxf(m2, Csh[(s * 32 + i) * LDC + r]);
            g_mx[(size_t)(colBase + r) * NSEGS + (rowBase >> 5) + s] = m2;
        }
    }
}

// ---------------------------------------------------------------------------
// 3) Per-row exact top-20 from precomputed segment maxes (+ sparse g_cos reads)
// ---------------------------------------------------------------------------
__global__ __launch_bounds__(256) void topk_loss_kernel(const int* __restrict__ labels) {
    __shared__ float s_max[256];
    __shared__ float s_cv[CAP];
    __shared__ int   s_ci[CAP];
    __shared__ int   s_cnt;
    __shared__ float s_t;

    const int row = blockIdx.x;
    const int tid = threadIdx.x;

    // Phase 1: one precomputed segment max per thread
    const float mx = g_mx[(size_t)row * NSEGS + tid];
    s_max[tid] = mx;
    if (tid == 0) s_cnt = 0;
    __syncthreads();

    // Phase 1.5: warp 0 computes the 20th-largest of the 256 segment maxes.
    // Segments are disjoint => the 20 largest seg-maxes are 20 distinct
    // elements >= t => top-20 of the row is contained in {v >= t}.
    if (tid < 32) {
        float m[8];
#pragma unroll
        for (int i = 0; i < 8; i++) m[i] = s_max[tid + 32 * i];
        float tlast = -3.0f;
        for (int rd = 0; rd < K_N; rd++) {
            float bv = m[0]; int bq = 0;
#pragma unroll
            for (int q = 1; q < 8; q++) if (m[q] > bv) { bv = m[q]; bq = q; }
            float v = bv; int li = tid;
#pragma unroll
            for (int s = 16; s > 0; s >>= 1) {
                float ov = __shfl_xor_sync(0xffffffffu, v, s);
                int   ol = __shfl_xor_sync(0xffffffffu, li, s);
                if (ov > v || (ov == v && ol < li)) { v = ov; li = ol; }
            }
            if (li == tid) {
#pragma unroll
                for (int q = 0; q < 8; q++) if (q == bq) m[q] = -3.0f;
            }
            tlast = v;
        }
        if (tid == 0) s_t = tlast;
    }
    __syncthreads();

    // Phase 2: only threads owning segments with max >= t read their 32 floats
    const float t = s_t;
    if (mx >= t) {
        const float4* sp = (const float4*)(g_cos + (size_t)row * B_N + tid * 32);
#pragma unroll
        for (int i = 0; i < 8; i++) {
            float4 v4 = sp[i];
            int c0 = tid * 32 + i * 4;
            float vv[4] = {v4.x, v4.y, v4.z, v4.w};
#pragma unroll
            for (int j = 0; j < 4; j++) {
                if (vv[j] >= t) {
                    int p = atomicAdd(&s_cnt, 1);
                    if (p < CAP) { s_cv[p] = vv[j]; s_ci[p] = c0 + j; }
                }
            }
        }
    }
    __syncthreads();

    // Phase 3: warp 0 — 20 exact argmax rounds over candidates + BCE
    if (tid < 32) {
        int nc = s_cnt; if (nc > CAP) nc = CAP;
        const int lab = labels[row];
        float rloss = 0.f;
        for (int rd = 0; rd < K_N; rd++) {
            float bv = -3.0f; int bp = -1;
            for (int p = tid; p < nc; p += 32) {
                float v = s_cv[p];
                if (v > bv) { bv = v; bp = p; }
            }
            float v = bv; int pi = bp;
#pragma unroll
            for (int s = 16; s > 0; s >>= 1) {
                float ov = __shfl_xor_sync(0xffffffffu, v, s);
                int   op = __shfl_xor_sync(0xffffffffu, pi, s);
                if (ov > v || (ov == v && op >= 0 && (pi < 0 || op < pi))) { v = ov; pi = op; }
            }
            if (tid == 0) {
                int col = s_ci[pi];
                float pred = 0.5f * (v + 1.0f);
                float lp = fmaxf(logf(pred), -100.0f);
                float l1 = fmaxf(log1pf(-pred), -100.0f);
                rloss += (labels[col] == lab) ? -lp : -l1;
                s_cv[pi] = -3.0f;
            }
            __syncwarp();
        }
        if (tid == 0) g_rowloss[row] = rloss;
    }
}

// ---------------------------------------------------------------------------
// 4) Deterministic final reduction over 8192 row losses
// ---------------------------------------------------------------------------
__global__ void reduce_kernel(float* __restrict__ out) {
    __shared__ double sh[256];
    int t = threadIdx.x;
    double s = 0.0;
    for (int i = t; i < B_N; i += 256) s += (double)g_rowloss[i];
    sh[t] = s;
    __syncthreads();
    for (int off = 128; off > 0; off >>= 1) {
        if (t < off) sh[t] += sh[t + off];
        __syncthreads();
    }
    if (t == 0) out[0] = (float)(sh[0] / (double)((long long)B_N * K_N));
}

// ---------------------------------------------------------------------------
extern "C" void kernel_launch(void* const* d_in, const int* in_sizes, int n_in,
                              void* d_out, int out_size) {
    const float* batch  = (const float*)d_in[0];
    const int*   labels = (const int*)d_in[1];
    float* out = (float*)d_out;
    (void)in_sizes; (void)n_in; (void)out_size;

    cudaFuncSetAttribute(gemm_sym_kernel, cudaFuncAttributeMaxDynamicSharedMemorySize,
                         SMEM_BYTES);

    normalize_kernel<<<B_N, 128>>>(batch);             // launch 1
    dummy_a_kernel<<<1, 32>>>();                       // launch 2
    dummy_b_kernel<<<1, 32>>>();                       // launch 3
    gemm_sym_kernel<<<NTILE, 512, SMEM_BYTES>>>();     // launch 4 -> ncu slot
    topk_loss_kernel<<<B_N, 256>>>(labels);            // launch 5
    reduce_kernel<<<1, 256>>>(out);                    // launch 6
}

// round 13
// speedup vs baseline: 1.6468x; 1.2731x over previous
#include <cuda_runtime.h>
#include <cuda_bf16.h>
#include <math.h>
#include <stdint.h>

// ---------------------------------------------------------------------------
// Problem constants
// ---------------------------------------------------------------------------
#define B_N 8192
#define D_N 512
#define K_N 20
#define NSEGS (B_N / 32)       // 256 column segments of 32

// GEMM tiling
#define BM 128
#define CK 64
#define NC (D_N / CK)
#define NBLK (B_N / BM)
#define NTILE (NBLK * (NBLK + 1) / 2)
#define LDC 129

#define STG_A 16384
#define STG_BUF 32768
#define SMEM_BYTES 66048

#define CAPW 448               // per-warp candidate buffer

// ---------------------------------------------------------------------------
// Scratch (__device__ globals — allocation-free)
// ---------------------------------------------------------------------------
__device__ __align__(128) __nv_bfloat16 g_xb[B_N * D_N];
__device__ __align__(128) float g_cos[(size_t)B_N * B_N];   // 268 MB
__device__ __align__(128) float g_mx[(size_t)B_N * NSEGS];  // 8 MB segment maxes
__device__ float g_rowloss[B_N];

// ---------------------------------------------------------------------------
// PTX helpers
// ---------------------------------------------------------------------------
__device__ __forceinline__ uint32_t smem_u32(const void* p) {
    uint32_t a;
    asm("{ .reg .u64 t; cvta.to.shared.u64 t, %1; cvt.u32.u64 %0, t; }" : "=r"(a) : "l"(p));
    return a;
}

__device__ __forceinline__ void cp_async16(uint32_t dst, const void* src) {
    asm volatile("cp.async.cg.shared.global [%0], [%1], 16;" :: "r"(dst), "l"(src) : "memory");
}
#define CP_COMMIT() asm volatile("cp.async.commit_group;" ::: "memory")
#define CP_WAIT1()  asm volatile("cp.async.wait_group 1;" ::: "memory")
#define CP_WAIT0()  asm volatile("cp.async.wait_group 0;" ::: "memory")

#define LDSM_X4(r0, r1, r2, r3, addr)                                        \
    asm volatile("ldmatrix.sync.aligned.m8n8.x4.shared.b16 {%0,%1,%2,%3}, [%4];" \
                 : "=r"(r0), "=r"(r1), "=r"(r2), "=r"(r3) : "r"(addr))

__device__ __forceinline__ void mma16816(float* c, uint32_t a0, uint32_t a1,
                                         uint32_t a2, uint32_t a3,
                                         uint32_t b0, uint32_t b1) {
    asm volatile(
        "mma.sync.aligned.m16n8k16.row.col.f32.bf16.bf16.f32 "
        "{%0,%1,%2,%3}, {%4,%5,%6,%7}, {%8,%9}, {%0,%1,%2,%3};"
        : "+f"(c[0]), "+f"(c[1]), "+f"(c[2]), "+f"(c[3])
        : "r"(a0), "r"(a1), "r"(a2), "r"(a3), "r"(b0), "r"(b1));
}

__global__ void dummy_a_kernel() {}

// ---------------------------------------------------------------------------
// 1) Row L2 normalization -> bf16
// ---------------------------------------------------------------------------
__global__ void normalize_kernel(const float* __restrict__ x) {
    __shared__ float warp_ss[4];
    __shared__ float s_inv;
    int row = blockIdx.x;
    int t = threadIdx.x;  // 128
    const float* xr = x + row * D_N;
    float v[4];
    float ss = 0.f;
#pragma unroll
    for (int i = 0; i < 4; i++) { v[i] = xr[t + 128 * i]; ss += v[i] * v[i]; }
#pragma unroll
    for (int off = 16; off > 0; off >>= 1) ss += __shfl_xor_sync(0xffffffffu, ss, off);
    if ((t & 31) == 0) warp_ss[t >> 5] = ss;
    __syncthreads();
    if (t == 0) {
        float tot = warp_ss[0] + warp_ss[1] + warp_ss[2] + warp_ss[3];
        s_inv = 1.0f / fmaxf(sqrtf(tot), 1e-12f);
    }
    __syncthreads();
    float inv = s_inv;
#pragma unroll
    for (int i = 0; i < 4; i++)
        g_xb[row * D_N + t + 128 * i] = __float2bfloat16_rn(v[i] * inv);
}

// ---------------------------------------------------------------------------
// 2) Symmetric bf16 mma.sync GEMM -> g_cos + per-32col segment maxes g_mx
//    (unchanged from R12; proven at ~187us)
// ---------------------------------------------------------------------------
extern __shared__ char smem_raw[];

__global__ __launch_bounds__(512, 1) void gemm_sym_kernel() {
    const int tid = threadIdx.x;
    const int lane = tid & 31;
    const int wid = tid >> 5;
    const int wm = wid & 3;
    const int wn = wid >> 2;

    int bi = 0, rem = blockIdx.x;
    while (rem >= NBLK - bi) { rem -= NBLK - bi; bi++; }
    const int bj = bi + rem;
    const int rowBase = bi * BM;
    const int colBase = bj * BM;

    const uint32_t sbase = smem_u32(smem_raw);
    float* Csh = (float*)smem_raw;

    uint32_t soff[2], grow[2];
#pragma unroll
    for (int i = 0; i < 2; i++) {
        int cid = tid + 512 * i;
        int r = cid >> 3, c16 = cid & 7;
        soff[i] = (uint32_t)(r * 128 + ((c16 * 16) ^ ((r & 7) << 4)));
        grow[i] = (uint32_t)(r * (D_N * 2) + c16 * 16);
    }
    const char* Agbase = (const char*)g_xb + (size_t)rowBase * D_N * 2;
    const char* Bgbase = (const char*)g_xb + (size_t)colBase * D_N * 2;

    const uint32_t rx = (uint32_t)((lane & 7) << 4);
    const uint32_t ah = (uint32_t)((lane >> 4) << 4);
    const uint32_t bh = (uint32_t)(((lane >> 3) & 1) << 4);
    const uint32_t arow0 = (uint32_t)((wm * 32 + (lane & 7) + ((lane >> 3) & 1) * 8) * 128);
    const uint32_t brow0 = (uint32_t)((wn * 32 + (lane & 7) + (lane >> 4) * 8) * 128);

    float acc[2][4][4];
#pragma unroll
    for (int mt = 0; mt < 2; mt++)
#pragma unroll
        for (int nt = 0; nt < 4; nt++)
#pragma unroll
            for (int q = 0; q < 4; q++) acc[mt][nt][q] = 0.f;

#pragma unroll
    for (int pc = 0; pc < 2; pc++) {
        uint32_t ab = sbase + pc * STG_BUF;
        const char* Ag = Agbase + pc * (CK * 2);
        const char* Bg = Bgbase + pc * (CK * 2);
#pragma unroll
        for (int i = 0; i < 2; i++) {
            cp_async16(ab + soff[i], Ag + grow[i]);
            cp_async16(ab + STG_A + soff[i], Bg + grow[i]);
        }
        CP_COMMIT();
    }

#pragma unroll
    for (int kc = 0; kc < NC; kc++) {
        if (kc == NC - 1) CP_WAIT0(); else CP_WAIT1();
        __syncthreads();

        const uint32_t ab = sbase + (kc & 1) * STG_BUF;
        const uint32_t bb = ab + STG_A;
#pragma unroll
        for (int ks = 0; ks < 4; ks++) {
            const uint32_t kbyte = (uint32_t)(ks * 32);
            uint32_t a[2][4], b[2][4];
#pragma unroll
            for (int mt = 0; mt < 2; mt++)
                LDSM_X4(a[mt][0], a[mt][1], a[mt][2], a[mt][3],
                        ab + arow0 + mt * 2048 + ((kbyte + ah) ^ rx));
#pragma unroll
            for (int np = 0; np < 2; np++)
                LDSM_X4(b[np][0], b[np][1], b[np][2], b[np][3],
                        bb + brow0 + np * 2048 + ((kbyte + bh) ^ rx));
#pragma unroll
            for (int mt = 0; mt < 2; mt++)
#pragma unroll
                for (int nt = 0; nt < 4; nt++)
                    mma16816(acc[mt][nt],
                             a[mt][0], a[mt][1], a[mt][2], a[mt][3],
                             b[nt >> 1][2 * (nt & 1)], b[nt >> 1][2 * (nt & 1) + 1]);
        }
        __syncthreads();

        if (kc + 2 < NC) {
            uint32_t ab2 = sbase + (kc & 1) * STG_BUF;
            const char* Ag = Agbase + (kc + 2) * (CK * 2);
            const char* Bg = Bgbase + (kc + 2) * (CK * 2);
#pragma unroll
            for (int i = 0; i < 2; i++) {
                cp_async16(ab2 + soff[i], Ag + grow[i]);
                cp_async16(ab2 + STG_A + soff[i], Bg + grow[i]);
            }
            CP_COMMIT();
        }
    }

    // dump accumulators to Csh
    {
        const int g = lane >> 2;
        const int c2 = 2 * (lane & 3);
#pragma unroll
        for (int mt = 0; mt < 2; mt++) {
            const int r0 = wm * 32 + mt * 16 + g;
#pragma unroll
            for (int nt = 0; nt < 4; nt++) {
                const int c0 = wn * 32 + nt * 8 + c2;
                Csh[r0 * LDC + c0]           = acc[mt][nt][0];
                Csh[r0 * LDC + c0 + 1]       = acc[mt][nt][1];
                Csh[(r0 + 8) * LDC + c0]     = acc[mt][nt][2];
                Csh[(r0 + 8) * LDC + c0 + 1] = acc[mt][nt][3];
            }
        }
    }
    __syncthreads();

    if (bi == bj && tid < BM) Csh[tid * LDC + tid] = -2.0f;
    __syncthreads();

#pragma unroll
    for (int i = 0; i < 8; i++) {
        int p = tid + 512 * i;
        int r = p >> 5;
        int c4 = (p & 31) * 4;
        float4 o;
        o.x = Csh[r * LDC + c4];
        o.y = Csh[r * LDC + c4 + 1];
        o.z = Csh[r * LDC + c4 + 2];
        o.w = Csh[r * LDC + c4 + 3];
        *(float4*)(g_cos + (size_t)(rowBase + r) * B_N + colBase + c4) = o;
    }

    if (bi != bj) {
#pragma unroll
        for (int i = 0; i < 8; i++) {
            int p = tid + 512 * i;
            int c = p >> 5;
            int r4 = (p & 31) * 4;
            float4 o;
            o.x = Csh[(r4 + 0) * LDC + c];
            o.y = Csh[(r4 + 1) * LDC + c];
            o.z = Csh[(r4 + 2) * LDC + c];
            o.w = Csh[(r4 + 3) * LDC + c];
            *(float4*)(g_cos + (size_t)(colBase + c) * B_N + rowBase + r4) = o;
        }
    }

    // 32-col segment maxes
    {
        const int r = tid >> 2;
        const int s = tid & 3;
        const float* base = Csh + r * LDC + s * 32;
        float m = base[0];
#pragma unroll
        for (int c = 1; c < 32; c++) m = fmaxf(m, base[c]);
        g_mx[(size_t)(rowBase + r) * NSEGS + (colBase >> 5) + s] = m;

        if (bi != bj) {
            float m2 = Csh[(s * 32) * LDC + r];
#pragma unroll
            for (int i = 1; i < 32; i++) m2 = fmaxf(m2, Csh[(s * 32 + i) * LDC + r]);
            g_mx[(size_t)(colBase + r) * NSEGS + (rowBase >> 5) + s] = m2;
        }
    }
}

// ---------------------------------------------------------------------------
// 3) Per-row exact top-20: one WARP per row (8 rows/block), warp-synchronous
// ---------------------------------------------------------------------------
__global__ __launch_bounds__(256) void topk_loss_kernel(const int* __restrict__ labels) {
    __shared__ float s_cv[8][CAPW];
    __shared__ int   s_ci[8][CAPW];

    const int w = threadIdx.x >> 5;
    const int lane = threadIdx.x & 31;
    const int row = blockIdx.x * 8 + w;

    // load this row's 256 segment maxes (8 per lane, coalesced)
    const float* mrow = g_mx + (size_t)row * NSEGS;
    float m[8];
#pragma unroll
    for (int i = 0; i < 8; i++) m[i] = mrow[lane + 32 * i];

    // threshold = 20th-largest of the 256 seg maxes (exact; disjoint segments
    // guarantee >= 20 distinct elements >= t, so row top-20 subset of {v>=t})
    float mm[8];
#pragma unroll
    for (int i = 0; i < 8; i++) mm[i] = m[i];
    float t = -3.0f;
    for (int rd = 0; rd < K_N; rd++) {
        float bv = mm[0]; int bq = 0;
#pragma unroll
        for (int q = 1; q < 8; q++) if (mm[q] > bv) { bv = mm[q]; bq = q; }
        float v = bv; int li = lane;
#pragma unroll
        for (int s = 16; s > 0; s >>= 1) {
            float ov = __shfl_xor_sync(0xffffffffu, v, s);
            int   ol = __shfl_xor_sync(0xffffffffu, li, s);
            if (ov > v || (ov == v && ol < li)) { v = ov; li = ol; }
        }
        if (li == lane) {
#pragma unroll
            for (int q = 0; q < 8; q++) if (q == bq) mm[q] = -3.0f;
        }
        t = v;
    }

    // phase 2: whole warp reads each qualifying segment; ballot-compact
    int cnt = 0;
    const float* rowp = g_cos + (size_t)row * B_N;
#pragma unroll
    for (int i = 0; i < 8; i++) {
        unsigned segmask = __ballot_sync(0xffffffffu, m[i] >= t);
        while (segmask) {
            int b = __ffs(segmask) - 1;
            segmask &= segmask - 1;
            int seg = b + 32 * i;
            float v = rowp[seg * 32 + lane];   // one coalesced 128B read
            bool keep = (v >= t);
            unsigned km = __ballot_sync(0xffffffffu, keep);
            if (keep) {
                int pos = cnt + __popc(km & ((1u << lane) - 1));
                if (pos < CAPW) { s_cv[w][pos] = v; s_ci[w][pos] = seg * 32 + lane; }
            }
            cnt += __popc(km);
        }
    }
    if (cnt > CAPW) cnt = CAPW;
    __syncwarp();

    // phase 3: 20 exact argmax rounds over candidates + BCE
    const int lab = labels[row];
    float rloss = 0.f;
    for (int rd = 0; rd < K_N; rd++) {
        float bv = -3.0f; int bp = -1;
        for (int p = lane; p < cnt; p += 32) {
            float v = s_cv[w][p];
            if (v > bv) { bv = v; bp = p; }
        }
        float v = bv; int pi = bp;
#pragma unroll
        for (int s = 16; s > 0; s >>= 1) {
            float ov = __shfl_xor_sync(0xffffffffu, v, s);
            int   op = __shfl_xor_sync(0xffffffffu, pi, s);
            if (ov > v || (ov == v && op >= 0 && (pi < 0 || op < pi))) { v = ov; pi = op; }
        }
        if (lane == 0) {
            int col = s_ci[w][pi];
            float pred = 0.5f * (v + 1.0f);
            float lp = fmaxf(logf(pred), -100.0f);
            float l1 = fmaxf(log1pf(-pred), -100.0f);
            rloss += (labels[col] == lab) ? -lp : -l1;
            s_cv[w][pi] = -3.0f;
        }
        __syncwarp();
    }
    if (lane == 0) g_rowloss[row] = rloss;
}

// ---------------------------------------------------------------------------
// 4) Deterministic final reduction over 8192 row losses
// ---------------------------------------------------------------------------
__global__ void reduce_kernel(float* __restrict__ out) {
    __shared__ double sh[256];
    int t = threadIdx.x;
    double s = 0.0;
    for (int i = t; i < B_N; i += 256) s += (double)g_rowloss[i];
    sh[t] = s;
    __syncthreads();
    for (int off = 128; off > 0; off >>= 1) {
        if (t < off) sh[t] += sh[t + off];
        __syncthreads();
    }
    if (t == 0) out[0] = (float)(sh[0] / (double)((long long)B_N * K_N));
}

// ---------------------------------------------------------------------------
extern "C" void kernel_launch(void* const* d_in, const int* in_sizes, int n_in,
                              void* d_out, int out_size) {
    const float* batch  = (const float*)d_in[0];
    const int*   labels = (const int*)d_in[1];
    float* out = (float*)d_out;
    (void)in_sizes; (void)n_in; (void)out_size;

    cudaFuncSetAttribute(gemm_sym_kernel, cudaFuncAttributeMaxDynamicSharedMemorySize,
                         SMEM_BYTES);

    normalize_kernel<<<B_N, 128>>>(batch);             // launch 1
    gemm_sym_kernel<<<NTILE, 512, SMEM_BYTES>>>();     // launch 2
    dummy_a_kernel<<<1, 32>>>();                       // launch 3 (slot shim)
    topk_loss_kernel<<<B_N / 8, 256>>>(labels);        // launch 4 -> ncu slot
    reduce_kernel<<<1, 256>>>(out);                    // launch 5
}

// round 14
// speedup vs baseline: 1.7407x; 1.0570x over previous
#include <cuda_runtime.h>
#include <cuda_bf16.h>
#include <math.h>
#include <stdint.h>

// ---------------------------------------------------------------------------
// Problem constants
// ---------------------------------------------------------------------------
#define B_N 8192
#define D_N 512
#define K_N 20
#define NSEGS (B_N / 32)       // 256 column segments of 32

// GEMM tiling: CTA 128x256, 16 warps of 32x64, K-chunk 64
#define CK 64
#define NC (D_N / CK)          // 8
#define NSUP (B_N / 256)       // 32 column superblocks
#define NTILE2 (NSUP * NSUP + NSUP)  // 1056 tiles (i <= 2J+1)
#define LDC 129

#define STG_A 16384            // A: 128x64 bf16
#define STG_B 32768            // B: 256x64 bf16
#define STG_BUF 49152
#define SMEM_BYTES 98304       // 2 stages; Csh (66048) reuses this

#define CAPW 448               // per-warp candidate buffer (topk)

// ---------------------------------------------------------------------------
// Scratch (__device__ globals — allocation-free)
// ---------------------------------------------------------------------------
__device__ __align__(128) __nv_bfloat16 g_xb[B_N * D_N];
__device__ __align__(128) float g_cos[(size_t)B_N * B_N];   // 268 MB
__device__ __align__(128) float g_mx[(size_t)B_N * NSEGS];  // 8 MB segment maxes
__device__ float g_rowloss[B_N];

// ---------------------------------------------------------------------------
// PTX helpers
// ---------------------------------------------------------------------------
__device__ __forceinline__ uint32_t smem_u32(const void* p) {
    uint32_t a;
    asm("{ .reg .u64 t; cvta.to.shared.u64 t, %1; cvt.u32.u64 %0, t; }" : "=r"(a) : "l"(p));
    return a;
}

__device__ __forceinline__ void cp_async16(uint32_t dst, const void* src) {
    asm volatile("cp.async.cg.shared.global [%0], [%1], 16;" :: "r"(dst), "l"(src) : "memory");
}
#define CP_COMMIT() asm volatile("cp.async.commit_group;" ::: "memory")
#define CP_WAIT1()  asm volatile("cp.async.wait_group 1;" ::: "memory")
#define CP_WAIT0()  asm volatile("cp.async.wait_group 0;" ::: "memory")

#define LDSM_X4(r0, r1, r2, r3, addr)                                        \
    asm volatile("ldmatrix.sync.aligned.m8n8.x4.shared.b16 {%0,%1,%2,%3}, [%4];" \
                 : "=r"(r0), "=r"(r1), "=r"(r2), "=r"(r3) : "r"(addr))

__device__ __forceinline__ void mma16816(float* c, uint32_t a0, uint32_t a1,
                                         uint32_t a2, uint32_t a3,
                                         uint32_t b0, uint32_t b1) {
    asm volatile(
        "mma.sync.aligned.m16n8k16.row.col.f32.bf16.bf16.f32 "
        "{%0,%1,%2,%3}, {%4,%5,%6,%7}, {%8,%9}, {%0,%1,%2,%3};"
        : "+f"(c[0]), "+f"(c[1]), "+f"(c[2]), "+f"(c[3])
        : "r"(a0), "r"(a1), "r"(a2), "r"(a3), "r"(b0), "r"(b1));
}

__global__ void dummy_a_kernel() {}
__global__ void dummy_b_kernel() {}

// ---------------------------------------------------------------------------
// 1) Row L2 normalization -> bf16
// ---------------------------------------------------------------------------
__global__ void normalize_kernel(const float* __restrict__ x) {
    __shared__ float warp_ss[4];
    __shared__ float s_inv;
    int row = blockIdx.x;
    int t = threadIdx.x;  // 128
    const float* xr = x + row * D_N;
    float v[4];
    float ss = 0.f;
#pragma unroll
    for (int i = 0; i < 4; i++) { v[i] = xr[t + 128 * i]; ss += v[i] * v[i]; }
#pragma unroll
    for (int off = 16; off > 0; off >>= 1) ss += __shfl_xor_sync(0xffffffffu, ss, off);
    if ((t & 31) == 0) warp_ss[t >> 5] = ss;
    __syncthreads();
    if (t == 0) {
        float tot = warp_ss[0] + warp_ss[1] + warp_ss[2] + warp_ss[3];
        s_inv = 1.0f / fmaxf(sqrtf(tot), 1e-12f);
    }
    __syncthreads();
    float inv = s_inv;
#pragma unroll
    for (int i = 0; i < 4; i++)
        g_xb[row * D_N + t + 128 * i] = __float2bfloat16_rn(v[i] * inv);
}

// ---------------------------------------------------------------------------
// 2) Symmetric bf16 GEMM, CTA 128x256, warp tile 32x64, triangular supertiles
// ---------------------------------------------------------------------------
extern __shared__ char smem_raw[];

__global__ __launch_bounds__(512, 1) void gemm_sym_kernel() {
    const int tid = threadIdx.x;
    const int lane = tid & 31;
    const int wid = tid >> 5;
    const int wm = wid & 3;        // M band: 32 rows
    const int wn = wid >> 2;       // N band: 64 cols

    // supertile decode: J = col superblock (256 wide), i = row block (128), i <= 2J+1
    int J = 0, rem = blockIdx.x;
    while (rem >= 2 * J + 2) { rem -= 2 * J + 2; J++; }
    const int ib = rem;
    const int rowBase = ib * 128;
    const int colSuper = J * 256;

    const uint32_t sbase = smem_u32(smem_raw);
    float* Csh = (float*)smem_raw;

    // cp.async staging map: 3072 16B chunks/stage; cid = tid + 512*i (i=0..5)
    // cid < 1024 -> A (128 rows), else B (256 rows). grow = absolute g_xb byte off.
    uint32_t soff[6], grow[6];
#pragma unroll
    for (int q = 0; q < 6; q++) {
        int cid = tid + 512 * q;
        int isB = (cid >= 1024);
        int r = (isB ? (cid - 1024) : cid) >> 3;
        int c16 = cid & 7;
        soff[q] = (uint32_t)(isB * STG_A + r * 128 + ((c16 * 16) ^ ((r & 7) << 4)));
        grow[q] = (uint32_t)(((isB ? colSuper : rowBase) + r) * (D_N * 2) + c16 * 16);
    }
    const char* gx = (const char*)g_xb;

    // ldmatrix addressing
    const uint32_t rx = (uint32_t)((lane & 7) << 4);
    const uint32_t ah = (uint32_t)((lane >> 4) << 4);
    const uint32_t bh = (uint32_t)(((lane >> 3) & 1) << 4);
    const uint32_t arow0 = (uint32_t)((wm * 32 + (lane & 7) + ((lane >> 3) & 1) * 8) * 128);
    const uint32_t brow0 = (uint32_t)((wn * 64 + (lane & 7) + (lane >> 4) * 8) * 128);

    float acc[2][8][4];
#pragma unroll
    for (int mt = 0; mt < 2; mt++)
#pragma unroll
        for (int nt = 0; nt < 8; nt++)
#pragma unroll
            for (int q = 0; q < 4; q++) acc[mt][nt][q] = 0.f;

    // prologue: stage chunks 0,1
#pragma unroll
    for (int pc = 0; pc < 2; pc++) {
        uint32_t ab = sbase + pc * STG_BUF;
#pragma unroll
        for (int q = 0; q < 6; q++)
            cp_async16(ab + soff[q], gx + grow[q] + pc * (CK * 2));
        CP_COMMIT();
    }

#pragma unroll
    for (int kc = 0; kc < NC; kc++) {
        if (kc == NC - 1) CP_WAIT0(); else CP_WAIT1();
        __syncthreads();

        const uint32_t ab = sbase + (kc & 1) * STG_BUF;
        const uint32_t bb = ab + STG_A;
#pragma unroll
        for (int ks = 0; ks < 4; ks++) {
            const uint32_t kbyte = (uint32_t)(ks * 32);
            uint32_t a[2][4], b[4][4];
#pragma unroll
            for (int mt = 0; mt < 2; mt++)
                LDSM_X4(a[mt][0], a[mt][1], a[mt][2], a[mt][3],
                        ab + arow0 + mt * 2048 + ((kbyte + ah) ^ rx));
#pragma unroll
            for (int np = 0; np < 4; np++)
                LDSM_X4(b[np][0], b[np][1], b[np][2], b[np][3],
                        bb + brow0 + np * 2048 + ((kbyte + bh) ^ rx));
#pragma unroll
            for (int mt = 0; mt < 2; mt++)
#pragma unroll
                for (int nt = 0; nt < 8; nt++)
                    mma16816(acc[mt][nt],
                             a[mt][0], a[mt][1], a[mt][2], a[mt][3],
                             b[nt >> 1][2 * (nt & 1)], b[nt >> 1][2 * (nt & 1) + 1]);
        }
        __syncthreads();

        if (kc + 2 < NC) {
            uint32_t ab2 = sbase + (kc & 1) * STG_BUF;
#pragma unroll
            for (int q = 0; q < 6; q++)
                cp_async16(ab2 + soff[q], gx + grow[q] + (kc + 2) * (CK * 2));
            CP_COMMIT();
        }
    }

    // Epilogue: two 128x128 column halves through Csh (reuses stage smem)
#pragma unroll
    for (int h = 0; h < 2; h++) {
        const int colblk = 2 * J + h;           // 128-col block index
        const int colBase = colblk * 128;
        __syncthreads();                         // Csh free (prev reads done)

        // dump: warps with wn>>1 == h own this half
        if ((wn >> 1) == h) {
            const int g = lane >> 2;
            const int c2 = 2 * (lane & 3);
#pragma unroll
            for (int mt = 0; mt < 2; mt++) {
                const int r0 = wm * 32 + mt * 16 + g;
#pragma unroll
                for (int nt = 0; nt < 8; nt++) {
                    const int c0 = (wn & 1) * 64 + nt * 8 + c2;
                    Csh[r0 * LDC + c0]           = acc[mt][nt][0];
                    Csh[r0 * LDC + c0 + 1]       = acc[mt][nt][1];
                    Csh[(r0 + 8) * LDC + c0]     = acc[mt][nt][2];
                    Csh[(r0 + 8) * LDC + c0 + 1] = acc[mt][nt][3];
                }
            }
        }
        __syncthreads();

        if (ib == colblk && tid < 128) Csh[tid * LDC + tid] = -2.0f;
        __syncthreads();

        if (ib <= colblk) {
            // direct store
#pragma unroll
            for (int q = 0; q < 8; q++) {
                int p = tid + 512 * q;
                int r = p >> 5;
                int c4 = (p & 31) * 4;
                float4 o;
                o.x = Csh[r * LDC + c4];
                o.y = Csh[r * LDC + c4 + 1];
                o.z = Csh[r * LDC + c4 + 2];
                o.w = Csh[r * LDC + c4 + 3];
                *(float4*)(g_cos + (size_t)(rowBase + r) * B_N + colBase + c4) = o;
            }
            // direct seg maxes
            {
                const int r = tid >> 2;
                const int s = tid & 3;
                const float* base = Csh + r * LDC + s * 32;
                float m = base[0];
#pragma unroll
                for (int c = 1; c < 32; c++) m = fmaxf(m, base[c]);
                g_mx[(size_t)(rowBase + r) * NSEGS + (colBase >> 5) + s] = m;
            }
        }
        if (ib < colblk) {
            // mirror store
#pragma unroll
            for (int q = 0; q < 8; q++) {
                int p = tid + 512 * q;
                int c = p >> 5;
                int r4 = (p & 31) * 4;
                float4 o;
                o.x = Csh[(r4 + 0) * LDC + c];
                o.y = Csh[(r4 + 1) * LDC + c];
                o.z = Csh[(r4 + 2) * LDC + c];
                o.w = Csh[(r4 + 3) * LDC + c];
                *(float4*)(g_cos + (size_t)(colBase + c) * B_N + rowBase + r4) = o;
            }
            // mirror seg maxes
            {
                const int r = tid >> 2;
                const int s = tid & 3;
                float m2 = Csh[(s * 32) * LDC + r];
#pragma unroll
                for (int c = 1; c < 32; c++) m2 = fmaxf(m2, Csh[(s * 32 + c) * LDC + r]);
                g_mx[(size_t)(colBase + r) * NSEGS + (rowBase >> 5) + s] = m2;
            }
        }
    }
}

// ---------------------------------------------------------------------------
// 3) Per-row exact top-20: one WARP per row (8 rows/block), warp-synchronous
// ---------------------------------------------------------------------------
__global__ __launch_bounds__(256) void topk_loss_kernel(const int* __restrict__ labels) {
    __shared__ float s_cv[8][CAPW];
    __shared__ int   s_ci[8][CAPW];

    const int w = threadIdx.x >> 5;
    const int lane = threadIdx.x & 31;
    const int row = blockIdx.x * 8 + w;

    const float* mrow = g_mx + (size_t)row * NSEGS;
    float m[8];
#pragma unroll
    for (int i = 0; i < 8; i++) m[i] = mrow[lane + 32 * i];

    // threshold = 20th-largest of 256 seg maxes (exact cover guarantee)
    float mm[8];
#pragma unroll
    for (int i = 0; i < 8; i++) mm[i] = m[i];
    float t = -3.0f;
    for (int rd = 0; rd < K_N; rd++) {
        float bv = mm[0]; int bq = 0;
#pragma unroll
        for (int q = 1; q < 8; q++) if (mm[q] > bv) { bv = mm[q]; bq = q; }
        float v = bv; int li = lane;
#pragma unroll
        for (int s = 16; s > 0; s >>= 1) {
            float ov = __shfl_xor_sync(0xffffffffu, v, s);
            int   ol = __shfl_xor_sync(0xffffffffu, li, s);
            if (ov > v || (ov == v && ol < li)) { v = ov; li = ol; }
        }
        if (li == lane) {
#pragma unroll
            for (int q = 0; q < 8; q++) if (q == bq) mm[q] = -3.0f;
        }
        t = v;
    }

    // collect candidates
    int cnt = 0;
    const float* rowp = g_cos + (size_t)row * B_N;
#pragma unroll
    for (int i = 0; i < 8; i++) {
        unsigned segmask = __ballot_sync(0xffffffffu, m[i] >= t);
        while (segmask) {
            int b = __ffs(segmask) - 1;
            segmask &= segmask - 1;
            int seg = b + 32 * i;
            float v = rowp[seg * 32 + lane];
            bool keep = (v >= t);
            unsigned km = __ballot_sync(0xffffffffu, keep);
            if (keep) {
                int pos = cnt + __popc(km & ((1u << lane) - 1));
                if (pos < CAPW) { s_cv[w][pos] = v; s_ci[w][pos] = seg * 32 + lane; }
            }
            cnt += __popc(km);
        }
    }
    if (cnt > CAPW) cnt = CAPW;
    __syncwarp();

    // 20 exact argmax rounds + BCE
    const int lab = labels[row];
    float rloss = 0.f;
    for (int rd = 0; rd < K_N; rd++) {
        float bv = -3.0f; int bp = -1;
        for (int p = lane; p < cnt; p += 32) {
            float v = s_cv[w][p];
            if (v > bv) { bv = v; bp = p; }
        }
        float v = bv; int pi = bp;
#pragma unroll
        for (int s = 16; s > 0; s >>= 1) {
            float ov = __shfl_xor_sync(0xffffffffu, v, s);
            int   op = __shfl_xor_sync(0xffffffffu, pi, s);
            if (ov > v || (ov == v && op >= 0 && (pi < 0 || op < pi))) { v = ov; pi = op; }
        }
        if (lane == 0) {
            int col = s_ci[w][pi];
            float pred = 0.5f * (v + 1.0f);
            float lp = fmaxf(logf(pred), -100.0f);
            float l1 = fmaxf(log1pf(-pred), -100.0f);
            rloss += (labels[col] == lab) ? -lp : -l1;
            s_cv[w][pi] = -3.0f;
        }
        __syncwarp();
    }
    if (lane == 0) g_rowloss[row] = rloss;
}

// ---------------------------------------------------------------------------
// 4) Deterministic final reduction
// ---------------------------------------------------------------------------
__global__ void reduce_kernel(float* __restrict__ out) {
    __shared__ double sh[256];
    int t = threadIdx.x;
    double s = 0.0;
    for (int i = t; i < B_N; i += 256) s += (double)g_rowloss[i];
    sh[t] = s;
    __syncthreads();
    for (int off = 128; off > 0; off >>= 1) {
        if (t < off) sh[t] += sh[t + off];
        __syncthreads();
    }
    if (t == 0) out[0] = (float)(sh[0] / (double)((long long)B_N * K_N));
}

// ---------------------------------------------------------------------------
extern "C" void kernel_launch(void* const* d_in, const int* in_sizes, int n_in,
                              void* d_out, int out_size) {
    const float* batch  = (const float*)d_in[0];
    const int*   labels = (const int*)d_in[1];
    float* out = (float*)d_out;
    (void)in_sizes; (void)n_in; (void)out_size;

    cudaFuncSetAttribute(gemm_sym_kernel, cudaFuncAttributeMaxDynamicSharedMemorySize,
                         SMEM_BYTES);

    normalize_kernel<<<B_N, 128>>>(batch);             // launch 1
    dummy_a_kernel<<<1, 32>>>();                       // launch 2
    dummy_b_kernel<<<1, 32>>>();                       // launch 3
    gemm_sym_kernel<<<NTILE2, 512, SMEM_BYTES>>>();    // launch 4 -> ncu slot
    topk_loss_kernel<<<B_N / 8, 256>>>(labels);        // launch 5
    reduce_kernel<<<1, 256>>>(out);                    // launch 6
}

// round 15
// speedup vs baseline: 1.8668x; 1.0725x over previous
#include <cuda_runtime.h>
#include <cuda_bf16.h>
#include <math.h>
#include <stdint.h>

// ---------------------------------------------------------------------------
// Problem constants
// ---------------------------------------------------------------------------
#define B_N 8192
#define D_N 512
#define K_N 20
#define NSEGS (B_N / 32)       // 256 column segments of 32

// GEMM tiling: CTA 128x128, 8 warps of 32x64, K-chunk 64, occupancy 2
#define BM 128
#define CK 64
#define NC (D_N / CK)          // 8
#define NBLK (B_N / BM)        // 64
#define NTILE (NBLK * (NBLK + 1) / 2)  // 2080 triangular tiles
#define LDC 129

#define STG_A 16384            // A: 128x64 bf16
#define STG_BUF 32768          // A+B per stage
#define SMEM_BYTES 66048       // max(2*STG_BUF=65536, Csh 128*129*4=66048)

#define CAPW 448               // per-warp candidate buffer (topk)

// ---------------------------------------------------------------------------
// Scratch (__device__ globals — allocation-free)
// ---------------------------------------------------------------------------
__device__ __align__(128) __nv_bfloat16 g_xb[B_N * D_N];
__device__ __align__(128) float g_cos[(size_t)B_N * B_N];   // 268 MB
__device__ __align__(128) float g_mx[(size_t)B_N * NSEGS];  // 8 MB segment maxes
__device__ float g_rowloss[B_N];

// ---------------------------------------------------------------------------
// PTX helpers
// ---------------------------------------------------------------------------
__device__ __forceinline__ uint32_t smem_u32(const void* p) {
    uint32_t a;
    asm("{ .reg .u64 t; cvta.to.shared.u64 t, %1; cvt.u32.u64 %0, t; }" : "=r"(a) : "l"(p));
    return a;
}

__device__ __forceinline__ void cp_async16(uint32_t dst, const void* src) {
    asm volatile("cp.async.cg.shared.global [%0], [%1], 16;" :: "r"(dst), "l"(src) : "memory");
}
#define CP_COMMIT() asm volatile("cp.async.commit_group;" ::: "memory")
#define CP_WAIT1()  asm volatile("cp.async.wait_group 1;" ::: "memory")
#define CP_WAIT0()  asm volatile("cp.async.wait_group 0;" ::: "memory")

#define LDSM_X4(r0, r1, r2, r3, addr)                                        \
    asm volatile("ldmatrix.sync.aligned.m8n8.x4.shared.b16 {%0,%1,%2,%3}, [%4];" \
                 : "=r"(r0), "=r"(r1), "=r"(r2), "=r"(r3) : "r"(addr))

__device__ __forceinline__ void mma16816(float* c, uint32_t a0, uint32_t a1,
                                         uint32_t a2, uint32_t a3,
                                         uint32_t b0, uint32_t b1) {
    asm volatile(
        "mma.sync.aligned.m16n8k16.row.col.f32.bf16.bf16.f32 "
        "{%0,%1,%2,%3}, {%4,%5,%6,%7}, {%8,%9}, {%0,%1,%2,%3};"
        : "+f"(c[0]), "+f"(c[1]), "+f"(c[2]), "+f"(c[3])
        : "r"(a0), "r"(a1), "r"(a2), "r"(a3), "r"(b0), "r"(b1));
}

__global__ void dummy_a_kernel() {}
__global__ void dummy_b_kernel() {}

// ---------------------------------------------------------------------------
// 1) Row L2 normalization -> bf16
// ---------------------------------------------------------------------------
__global__ void normalize_kernel(const float* __restrict__ x) {
    __shared__ float warp_ss[4];
    __shared__ float s_inv;
    int row = blockIdx.x;
    int t = threadIdx.x;  // 128
    const float* xr = x + row * D_N;
    float v[4];
    float ss = 0.f;
#pragma unroll
    for (int i = 0; i < 4; i++) { v[i] = xr[t + 128 * i]; ss += v[i] * v[i]; }
#pragma unroll
    for (int off = 16; off > 0; off >>= 1) ss += __shfl_xor_sync(0xffffffffu, ss, off);
    if ((t & 31) == 0) warp_ss[t >> 5] = ss;
    __syncthreads();
    if (t == 0) {
        float tot = warp_ss[0] + warp_ss[1] + warp_ss[2] + warp_ss[3];
        s_inv = 1.0f / fmaxf(sqrtf(tot), 1e-12f);
    }
    __syncthreads();
    float inv = s_inv;
#pragma unroll
    for (int i = 0; i < 4; i++)
        g_xb[row * D_N + t + 128 * i] = __float2bfloat16_rn(v[i] * inv);
}

// ---------------------------------------------------------------------------
// 2) Symmetric bf16 GEMM: CTA 128x128, 8 warps of 32x64, 2-stage, occupancy 2
// ---------------------------------------------------------------------------
extern __shared__ char smem_raw[];

__global__ __launch_bounds__(256, 2) void gemm_sym_kernel() {
    const int tid = threadIdx.x;
    const int lane = tid & 31;
    const int wid = tid >> 5;
    const int wm = wid & 3;        // M band: 32 rows (4 bands)
    const int wn = wid >> 2;       // N band: 64 cols (2 bands)

    int bi = 0, rem = blockIdx.x;
    while (rem >= NBLK - bi) { rem -= NBLK - bi; bi++; }
    const int bj = bi + rem;
    const int rowBase = bi * BM;
    const int colBase = bj * BM;

    const uint32_t sbase = smem_u32(smem_raw);
    float* Csh = (float*)smem_raw;

    // staging: lean addressing (2 smem bases + 2 global bases, const offsets)
    const uint32_t sA = (uint32_t)((tid >> 3) * 128 +
                        (((tid & 7) * 16) ^ (((tid >> 3) & 7) << 4)));
    const char* gx = (const char*)g_xb;
    const char* gA = gx + (size_t)(rowBase + (tid >> 3)) * (D_N * 2) + (tid & 7) * 16;
    const char* gB = gx + (size_t)(colBase + (tid >> 3)) * (D_N * 2) + (tid & 7) * 16;

    // ldmatrix addressing
    const uint32_t rx = (uint32_t)((lane & 7) << 4);
    const uint32_t ah = (uint32_t)((lane >> 4) << 4);
    const uint32_t bh = (uint32_t)(((lane >> 3) & 1) << 4);
    const uint32_t arow0 = (uint32_t)((wm * 32 + (lane & 7) + ((lane >> 3) & 1) * 8) * 128);
    const uint32_t brow0 = (uint32_t)((wn * 64 + (lane & 7) + (lane >> 4) * 8) * 128);

    float acc[2][8][4];
#pragma unroll
    for (int mt = 0; mt < 2; mt++)
#pragma unroll
        for (int nt = 0; nt < 8; nt++)
#pragma unroll
            for (int q = 0; q < 4; q++) acc[mt][nt][q] = 0.f;

    // prologue: stage chunks 0,1  (32 rows per q-step: smem +4096, gmem +32*1024)
#pragma unroll
    for (int pc = 0; pc < 2; pc++) {
        uint32_t ab = sbase + pc * STG_BUF;
#pragma unroll
        for (int q = 0; q < 4; q++) {
            cp_async16(ab + sA + q * 4096, gA + pc * 128 + q * 32768);
            cp_async16(ab + STG_A + sA + q * 4096, gB + pc * 128 + q * 32768);
        }
        CP_COMMIT();
    }

#pragma unroll
    for (int kc = 0; kc < NC; kc++) {
        if (kc == NC - 1) CP_WAIT0(); else CP_WAIT1();
        __syncthreads();

        const uint32_t ab = sbase + (kc & 1) * STG_BUF;
        const uint32_t bb = ab + STG_A;
#pragma unroll
        for (int ks = 0; ks < 4; ks++) {
            const uint32_t kbyte = (uint32_t)(ks * 32);
            uint32_t a[2][4], b[4][4];
#pragma unroll
            for (int mt = 0; mt < 2; mt++)
                LDSM_X4(a[mt][0], a[mt][1], a[mt][2], a[mt][3],
                        ab + arow0 + mt * 2048 + ((kbyte + ah) ^ rx));
#pragma unroll
            for (int np = 0; np < 4; np++)
                LDSM_X4(b[np][0], b[np][1], b[np][2], b[np][3],
                        bb + brow0 + np * 2048 + ((kbyte + bh) ^ rx));
#pragma unroll
            for (int mt = 0; mt < 2; mt++)
#pragma unroll
                for (int nt = 0; nt < 8; nt++)
                    mma16816(acc[mt][nt],
                             a[mt][0], a[mt][1], a[mt][2], a[mt][3],
                             b[nt >> 1][2 * (nt & 1)], b[nt >> 1][2 * (nt & 1) + 1]);
        }
        __syncthreads();

        if (kc + 2 < NC) {
            uint32_t ab2 = sbase + (kc & 1) * STG_BUF;
#pragma unroll
            for (int q = 0; q < 4; q++) {
                cp_async16(ab2 + sA + q * 4096, gA + (kc + 2) * 128 + q * 32768);
                cp_async16(ab2 + STG_A + sA + q * 4096, gB + (kc + 2) * 128 + q * 32768);
            }
            CP_COMMIT();
        }
    }

    // dump accumulators to Csh (full 128x128)
    {
        const int g = lane >> 2;
        const int c2 = 2 * (lane & 3);
#pragma unroll
        for (int mt = 0; mt < 2; mt++) {
            const int r0 = wm * 32 + mt * 16 + g;
#pragma unroll
            for (int nt = 0; nt < 8; nt++) {
                const int c0 = wn * 64 + nt * 8 + c2;
                Csh[r0 * LDC + c0]           = acc[mt][nt][0];
                Csh[r0 * LDC + c0 + 1]       = acc[mt][nt][1];
                Csh[(r0 + 8) * LDC + c0]     = acc[mt][nt][2];
                Csh[(r0 + 8) * LDC + c0 + 1] = acc[mt][nt][3];
            }
        }
    }
    __syncthreads();

    if (bi == bj && tid < BM) Csh[tid * LDC + tid] = -2.0f;
    __syncthreads();

    // direct store (16 float4 per thread)
#pragma unroll
    for (int q = 0; q < 16; q++) {
        int p = tid + 256 * q;
        int r = p >> 5;
        int c4 = (p & 31) * 4;
        float4 o;
        o.x = Csh[r * LDC + c4];
        o.y = Csh[r * LDC + c4 + 1];
        o.z = Csh[r * LDC + c4 + 2];
        o.w = Csh[r * LDC + c4 + 3];
        *(float4*)(g_cos + (size_t)(rowBase + r) * B_N + colBase + c4) = o;
    }
    // direct seg maxes (512 row-seg pairs, 2 per thread)
#pragma unroll
    for (int q = 0; q < 2; q++) {
        int p = tid + 256 * q;
        int r = p >> 2;
        int s = p & 3;
        const float* base = Csh + r * LDC + s * 32;
        float m = base[0];
#pragma unroll
        for (int c = 1; c < 32; c++) m = fmaxf(m, base[c]);
        g_mx[(size_t)(rowBase + r) * NSEGS + (colBase >> 5) + s] = m;
    }

    if (bi != bj) {
        // mirror store (transposed)
#pragma unroll
        for (int q = 0; q < 16; q++) {
            int p = tid + 256 * q;
            int c = p >> 5;
            int r4 = (p & 31) * 4;
            float4 o;
            o.x = Csh[(r4 + 0) * LDC + c];
            o.y = Csh[(r4 + 1) * LDC + c];
            o.z = Csh[(r4 + 2) * LDC + c];
            o.w = Csh[(r4 + 3) * LDC + c];
            *(float4*)(g_cos + (size_t)(colBase + c) * B_N + rowBase + r4) = o;
        }
        // mirror seg maxes (column maxes)
#pragma unroll
        for (int q = 0; q < 2; q++) {
            int p = tid + 256 * q;
            int r = p >> 2;          // mirror row (= direct col)
            int s = p & 3;
            float m2 = Csh[(s * 32) * LDC + r];
#pragma unroll
            for (int c = 1; c < 32; c++) m2 = fmaxf(m2, Csh[(s * 32 + c) * LDC + r]);
            g_mx[(size_t)(colBase + r) * NSEGS + (rowBase >> 5) + s] = m2;
        }
    }
}

// ---------------------------------------------------------------------------
// 3) Per-row exact top-20: one WARP per row (8 rows/block), warp-synchronous
// ---------------------------------------------------------------------------
__global__ __launch_bounds__(256) void topk_loss_kernel(const int* __restrict__ labels) {
    __shared__ float s_cv[8][CAPW];
    __shared__ int   s_ci[8][CAPW];

    const int w = threadIdx.x >> 5;
    const int lane = threadIdx.x & 31;
    const int row = blockIdx.x * 8 + w;

    const float* mrow = g_mx + (size_t)row * NSEGS;
    float m[8];
#pragma unroll
    for (int i = 0; i < 8; i++) m[i] = mrow[lane + 32 * i];

    // threshold = 20th-largest of 256 seg maxes (exact cover guarantee)
    float mm[8];
#pragma unroll
    for (int i = 0; i < 8; i++) mm[i] = m[i];
    float t = -3.0f;
    for (int rd = 0; rd < K_N; rd++) {
        float bv = mm[0]; int bq = 0;
#pragma unroll
        for (int q = 1; q < 8; q++) if (mm[q] > bv) { bv = mm[q]; bq = q; }
        float v = bv; int li = lane;
#pragma unroll
        for (int s = 16; s > 0; s >>= 1) {
            float ov = __shfl_xor_sync(0xffffffffu, v, s);
            int   ol = __shfl_xor_sync(0xffffffffu, li, s);
            if (ov > v || (ov == v && ol < li)) { v = ov; li = ol; }
        }
        if (li == lane) {
#pragma unroll
            for (int q = 0; q < 8; q++) if (q == bq) mm[q] = -3.0f;
        }
        t = v;
    }

    // collect candidates (whole warp per qualifying segment)
    int cnt = 0;
    const float* rowp = g_cos + (size_t)row * B_N;
#pragma unroll
    for (int i = 0; i < 8; i++) {
        unsigned segmask = __ballot_sync(0xffffffffu, m[i] >= t);
        while (segmask) {
            int b = __ffs(segmask) - 1;
            segmask &= segmask - 1;
            int seg = b + 32 * i;
            float v = rowp[seg * 32 + lane];
            bool keep = (v >= t);
            unsigned km = __ballot_sync(0xffffffffu, keep);
            if (keep) {
                int pos = cnt + __popc(km & ((1u << lane) - 1));
                if (pos < CAPW) { s_cv[w][pos] = v; s_ci[w][pos] = seg * 32 + lane; }
            }
            cnt += __popc(km);
        }
    }
    if (cnt > CAPW) cnt = CAPW;
    __syncwarp();

    // 20 exact argmax rounds + BCE
    const int lab = labels[row];
    float rloss = 0.f;
    for (int rd = 0; rd < K_N; rd++) {
        float bv = -3.0f; int bp = -1;
        for (int p = lane; p < cnt; p += 32) {
            float v = s_cv[w][p];
            if (v > bv) { bv = v; bp = p; }
        }
        float v = bv; int pi = bp;
#pragma unroll
        for (int s = 16; s > 0; s >>= 1) {
            float ov = __shfl_xor_sync(0xffffffffu, v, s);
            int   op = __shfl_xor_sync(0xffffffffu, pi, s);
            if (ov > v || (ov == v && op >= 0 && (pi < 0 || op < pi))) { v = ov; pi = op; }
        }
        if (lane == 0) {
            int col = s_ci[w][pi];
            float pred = 0.5f * (v + 1.0f);
            float lp = fmaxf(logf(pred), -100.0f);
            float l1 = fmaxf(log1pf(-pred), -100.0f);
            rloss += (labels[col] == lab) ? -lp : -l1;
            s_cv[w][pi] = -3.0f;
        }
        __syncwarp();
    }
    if (lane == 0) g_rowloss[row] = rloss;
}

// ---------------------------------------------------------------------------
// 4) Deterministic final reduction
// ---------------------------------------------------------------------------
__global__ void reduce_kernel(float* __restrict__ out) {
    __shared__ double sh[256];
    int t = threadIdx.x;
    double s = 0.0;
    for (int i = t; i < B_N; i += 256) s += (double)g_rowloss[i];
    sh[t] = s;
    __syncthreads();
    for (int off = 128; off > 0; off >>= 1) {
        if (t < off) sh[t] += sh[t + off];
        __syncthreads();
    }
    if (t == 0) out[0] = (float)(sh[0] / (double)((long long)B_N * K_N));
}

// ---------------------------------------------------------------------------
extern "C" void kernel_launch(void* const* d_in, const int* in_sizes, int n_in,
                              void* d_out, int out_size) {
    const float* batch  = (const float*)d_in[0];
    const int*   labels = (const int*)d_in[1];
    float* out = (float*)d_out;
    (void)in_sizes; (void)n_in; (void)out_size;

    cudaFuncSetAttribute(gemm_sym_kernel, cudaFuncAttributeMaxDynamicSharedMemorySize,
                         SMEM_BYTES);

    normalize_kernel<<<B_N, 128>>>(batch);             // launch 1
    dummy_a_kernel<<<1, 32>>>();                       // launch 2
    dummy_b_kernel<<<1, 32>>>();                       // launch 3
    gemm_sym_kernel<<<NTILE, 256, SMEM_BYTES>>>();     // launch 4 -> ncu slot
    topk_loss_kernel<<<B_N / 8, 256>>>(labels);        // launch 5
    reduce_kernel<<<1, 256>>>(out);                    // launch 6
}

// round 16
// speedup vs baseline: 2.0967x; 1.1231x over previous
#include <cuda_runtime.h>
#include <cuda_bf16.h>
#include <math.h>
#include <stdint.h>

// ---------------------------------------------------------------------------
// Problem constants
// ---------------------------------------------------------------------------
#define B_N 8192
#define D_N 512
#define K_N 20
#define NSEGS (B_N / 32)       // 256 column segments of 32

// GEMM tiling: CTA 128x128, 8 warps of 32x64, K-chunk 64, occupancy 2
#define BM 128
#define CK 64
#define NC (D_N / CK)          // 8
#define NBLK (B_N / BM)        // 64
#define NTILE (NBLK * (NBLK + 1) / 2)  // 2080 triangular tiles
#define LDC 129

#define STG_A 16384            // A: 128x64 bf16
#define STG_BUF 32768          // A+B per stage
#define SMEM_BYTES 66048       // max(2*STG_BUF=65536, Csh 128*129*4=66048)

#define CAPW 448               // per-warp candidate buffer (topk)

// ---------------------------------------------------------------------------
// Scratch (__device__ globals — allocation-free)
// ---------------------------------------------------------------------------
__device__ __align__(128) __nv_bfloat16 g_xb[B_N * D_N];
__device__ __align__(128) float g_cos[(size_t)B_N * B_N];   // 268 MB
__device__ __align__(128) float g_mx[(size_t)B_N * NSEGS];  // 8 MB segment maxes
__device__ float g_rowloss[B_N];

// ---------------------------------------------------------------------------
// PTX helpers
// ---------------------------------------------------------------------------
__device__ __forceinline__ uint32_t smem_u32(const void* p) {
    uint32_t a;
    asm("{ .reg .u64 t; cvta.to.shared.u64 t, %1; cvt.u32.u64 %0, t; }" : "=r"(a) : "l"(p));
    return a;
}

__device__ __forceinline__ void cp_async16(uint32_t dst, const void* src) {
    asm volatile("cp.async.cg.shared.global [%0], [%1], 16;" :: "r"(dst), "l"(src) : "memory");
}
#define CP_COMMIT() asm volatile("cp.async.commit_group;" ::: "memory")
#define CP_WAIT1()  asm volatile("cp.async.wait_group 1;" ::: "memory")
#define CP_WAIT0()  asm volatile("cp.async.wait_group 0;" ::: "memory")

#define LDSM_X4(r0, r1, r2, r3, addr)                                        \
    asm volatile("ldmatrix.sync.aligned.m8n8.x4.shared.b16 {%0,%1,%2,%3}, [%4];" \
                 : "=r"(r0), "=r"(r1), "=r"(r2), "=r"(r3) : "r"(addr))

__device__ __forceinline__ void mma16816(float* c, uint32_t a0, uint32_t a1,
                                         uint32_t a2, uint32_t a3,
                                         uint32_t b0, uint32_t b1) {
    asm volatile(
        "mma.sync.aligned.m16n8k16.row.col.f32.bf16.bf16.f32 "
        "{%0,%1,%2,%3}, {%4,%5,%6,%7}, {%8,%9}, {%0,%1,%2,%3};"
        : "+f"(c[0]), "+f"(c[1]), "+f"(c[2]), "+f"(c[3])
        : "r"(a0), "r"(a1), "r"(a2), "r"(a3), "r"(b0), "r"(b1));
}

__global__ void dummy_a_kernel() {}
__global__ void dummy_b_kernel() {}

// ---------------------------------------------------------------------------
// 1) Row L2 normalization -> bf16
// ---------------------------------------------------------------------------
__global__ void normalize_kernel(const float* __restrict__ x) {
    __shared__ float warp_ss[4];
    __shared__ float s_inv;
    int row = blockIdx.x;
    int t = threadIdx.x;  // 128
    const float* xr = x + row * D_N;
    float v[4];
    float ss = 0.f;
#pragma unroll
    for (int i = 0; i < 4; i++) { v[i] = xr[t + 128 * i]; ss += v[i] * v[i]; }
#pragma unroll
    for (int off = 16; off > 0; off >>= 1) ss += __shfl_xor_sync(0xffffffffu, ss, off);
    if ((t & 31) == 0) warp_ss[t >> 5] = ss;
    __syncthreads();
    if (t == 0) {
        float tot = warp_ss[0] + warp_ss[1] + warp_ss[2] + warp_ss[3];
        s_inv = 1.0f / fmaxf(sqrtf(tot), 1e-12f);
    }
    __syncthreads();
    float inv = s_inv;
#pragma unroll
    for (int i = 0; i < 4; i++)
        g_xb[row * D_N + t + 128 * i] = __float2bfloat16_rn(v[i] * inv);
}

// ---------------------------------------------------------------------------
// 2) Symmetric bf16 GEMM: CTA 128x128, 8 warps of 32x64, 2-stage, occupancy 2
//    Epilogue: direct stores + seg maxes FROM REGISTERS; Csh only for mirror
// ---------------------------------------------------------------------------
extern __shared__ char smem_raw[];

__global__ __launch_bounds__(256, 2) void gemm_sym_kernel() {
    const int tid = threadIdx.x;
    const int lane = tid & 31;
    const int wid = tid >> 5;
    const int wm = wid & 3;        // M band: 32 rows (4 bands)
    const int wn = wid >> 2;       // N band: 64 cols (2 bands)

    int bi = 0, rem = blockIdx.x;
    while (rem >= NBLK - bi) { rem -= NBLK - bi; bi++; }
    const int bj = bi + rem;
    const int rowBase = bi * BM;
    const int colBase = bj * BM;

    const uint32_t sbase = smem_u32(smem_raw);
    float* Csh = (float*)smem_raw;

    // staging: lean addressing
    const uint32_t sA = (uint32_t)((tid >> 3) * 128 +
                        (((tid & 7) * 16) ^ (((tid >> 3) & 7) << 4)));
    const char* gx = (const char*)g_xb;
    const char* gA = gx + (size_t)(rowBase + (tid >> 3)) * (D_N * 2) + (tid & 7) * 16;
    const char* gB = gx + (size_t)(colBase + (tid >> 3)) * (D_N * 2) + (tid & 7) * 16;

    // ldmatrix addressing
    const uint32_t rx = (uint32_t)((lane & 7) << 4);
    const uint32_t ah = (uint32_t)((lane >> 4) << 4);
    const uint32_t bh = (uint32_t)(((lane >> 3) & 1) << 4);
    const uint32_t arow0 = (uint32_t)((wm * 32 + (lane & 7) + ((lane >> 3) & 1) * 8) * 128);
    const uint32_t brow0 = (uint32_t)((wn * 64 + (lane & 7) + (lane >> 4) * 8) * 128);

    float acc[2][8][4];
#pragma unroll
    for (int mt = 0; mt < 2; mt++)
#pragma unroll
        for (int nt = 0; nt < 8; nt++)
#pragma unroll
            for (int q = 0; q < 4; q++) acc[mt][nt][q] = 0.f;

    // prologue: stage chunks 0,1
#pragma unroll
    for (int pc = 0; pc < 2; pc++) {
        uint32_t ab = sbase + pc * STG_BUF;
#pragma unroll
        for (int q = 0; q < 4; q++) {
            cp_async16(ab + sA + q * 4096, gA + pc * 128 + q * 32768);
            cp_async16(ab + STG_A + sA + q * 4096, gB + pc * 128 + q * 32768);
        }
        CP_COMMIT();
    }

#pragma unroll
    for (int kc = 0; kc < NC; kc++) {
        if (kc == NC - 1) CP_WAIT0(); else CP_WAIT1();
        __syncthreads();

        const uint32_t ab = sbase + (kc & 1) * STG_BUF;
        const uint32_t bb = ab + STG_A;
#pragma unroll
        for (int ks = 0; ks < 4; ks++) {
            const uint32_t kbyte = (uint32_t)(ks * 32);
            uint32_t a[2][4], b[4][4];
#pragma unroll
            for (int mt = 0; mt < 2; mt++)
                LDSM_X4(a[mt][0], a[mt][1], a[mt][2], a[mt][3],
                        ab + arow0 + mt * 2048 + ((kbyte + ah) ^ rx));
#pragma unroll
            for (int np = 0; np < 4; np++)
                LDSM_X4(b[np][0], b[np][1], b[np][2], b[np][3],
                        bb + brow0 + np * 2048 + ((kbyte + bh) ^ rx));
#pragma unroll
            for (int mt = 0; mt < 2; mt++)
#pragma unroll
                for (int nt = 0; nt < 8; nt++)
                    mma16816(acc[mt][nt],
                             a[mt][0], a[mt][1], a[mt][2], a[mt][3],
                             b[nt >> 1][2 * (nt & 1)], b[nt >> 1][2 * (nt & 1) + 1]);
        }
        __syncthreads();

        if (kc + 2 < NC) {
            uint32_t ab2 = sbase + (kc & 1) * STG_BUF;
#pragma unroll
            for (int q = 0; q < 4; q++) {
                cp_async16(ab2 + sA + q * 4096, gA + (kc + 2) * 128 + q * 32768);
                cp_async16(ab2 + STG_A + sA + q * 4096, gB + (kc + 2) * 128 + q * 32768);
            }
            CP_COMMIT();
        }
    }

    const int g = lane >> 2;
    const int c2 = 2 * (lane & 3);

    // diagonal sentinel: predicate accumulators in-register (diag tiles only)
    if (bi == bj) {
#pragma unroll
        for (int mt = 0; mt < 2; mt++) {
            const int r0 = wm * 32 + mt * 16 + g;
#pragma unroll
            for (int nt = 0; nt < 8; nt++) {
                const int c0 = wn * 64 + nt * 8 + c2;
                if (r0 == c0)         acc[mt][nt][0] = -2.0f;
                if (r0 == c0 + 1)     acc[mt][nt][1] = -2.0f;
                if (r0 + 8 == c0)     acc[mt][nt][2] = -2.0f;
                if (r0 + 8 == c0 + 1) acc[mt][nt][3] = -2.0f;
            }
        }
    }

    // direct store straight from registers (sector-efficient float2 quads)
#pragma unroll
    for (int mt = 0; mt < 2; mt++) {
        const int r0 = wm * 32 + mt * 16 + g;
#pragma unroll
        for (int nt = 0; nt < 8; nt++) {
            const int c0 = wn * 64 + nt * 8 + c2;
            size_t base = (size_t)(rowBase + r0) * B_N + colBase + c0;
            float2 v01 = make_float2(acc[mt][nt][0], acc[mt][nt][1]);
            float2 v23 = make_float2(acc[mt][nt][2], acc[mt][nt][3]);
            *(float2*)(g_cos + base) = v01;
            *(float2*)(g_cos + base + (size_t)8 * B_N) = v23;
        }
    }

    // direct seg maxes from registers (quad shfl reduction; lanes share g)
#pragma unroll
    for (int mt = 0; mt < 2; mt++) {
        float mA0 = -3.f, mA1 = -3.f, mB0 = -3.f, mB1 = -3.f;
#pragma unroll
        for (int nt = 0; nt < 8; nt++) {
            float ma = fmaxf(acc[mt][nt][0], acc[mt][nt][1]);
            float mb = fmaxf(acc[mt][nt][2], acc[mt][nt][3]);
            if (nt < 4) { mA0 = fmaxf(mA0, ma); mB0 = fmaxf(mB0, mb); }
            else        { mA1 = fmaxf(mA1, ma); mB1 = fmaxf(mB1, mb); }
        }
#pragma unroll
        for (int s = 1; s <= 2; s <<= 1) {
            mA0 = fmaxf(mA0, __shfl_xor_sync(0xffffffffu, mA0, s));
            mA1 = fmaxf(mA1, __shfl_xor_sync(0xffffffffu, mA1, s));
            mB0 = fmaxf(mB0, __shfl_xor_sync(0xffffffffu, mB0, s));
            mB1 = fmaxf(mB1, __shfl_xor_sync(0xffffffffu, mB1, s));
        }
        if ((lane & 3) == 0) {
            const int r0 = wm * 32 + mt * 16 + g;
            size_t mb0 = (size_t)(rowBase + r0) * NSEGS + (colBase >> 5) + 2 * wn;
            g_mx[mb0] = mA0;
            g_mx[mb0 + 1] = mA1;
            size_t mb1 = (size_t)(rowBase + r0 + 8) * NSEGS + (colBase >> 5) + 2 * wn;
            g_mx[mb1] = mB0;
            g_mx[mb1 + 1] = mB1;
        }
    }

    // mirror path (off-diagonal only): Csh transpose + folded seg maxes
    if (bi != bj) {
        __syncthreads();   // stage smem reads all done (last mainloop sync also covers)
#pragma unroll
        for (int mt = 0; mt < 2; mt++) {
            const int r0 = wm * 32 + mt * 16 + g;
#pragma unroll
            for (int nt = 0; nt < 8; nt++) {
                const int c0 = wn * 64 + nt * 8 + c2;
                Csh[r0 * LDC + c0]           = acc[mt][nt][0];
                Csh[r0 * LDC + c0 + 1]       = acc[mt][nt][1];
                Csh[(r0 + 8) * LDC + c0]     = acc[mt][nt][2];
                Csh[(r0 + 8) * LDC + c0 + 1] = acc[mt][nt][3];
            }
        }
        __syncthreads();

        // transposed store + folded mirror seg maxes
#pragma unroll
        for (int q = 0; q < 16; q++) {
            int p = tid + 256 * q;
            int c = p >> 5;              // column (constant per warp per q)
            int r4 = (p & 31) * 4;       // 4 consecutive rows, one segment
            float v0 = Csh[(r4 + 0) * LDC + c];
            float v1 = Csh[(r4 + 1) * LDC + c];
            float v2 = Csh[(r4 + 2) * LDC + c];
            float v3 = Csh[(r4 + 3) * LDC + c];
            float4 o = make_float4(v0, v1, v2, v3);
            *(float4*)(g_cos + (size_t)(colBase + c) * B_N + rowBase + r4) = o;
            float tm = fmaxf(fmaxf(v0, v1), fmaxf(v2, v3));
#pragma unroll
            for (int s = 1; s <= 4; s <<= 1)
                tm = fmaxf(tm, __shfl_xor_sync(0xffffffffu, tm, s));
            if ((lane & 7) == 0)
                g_mx[(size_t)(colBase + c) * NSEGS + (rowBase >> 5) + ((p & 31) >> 3)] = tm;
        }
    }
}

// ---------------------------------------------------------------------------
// 3) Per-row exact top-20: one WARP per row (8 rows/block), warp-synchronous
// ---------------------------------------------------------------------------
__global__ __launch_bounds__(256) void topk_loss_kernel(const int* __restrict__ labels) {
    __shared__ float s_cv[8][CAPW];
    __shared__ int   s_ci[8][CAPW];

    const int w = threadIdx.x >> 5;
    const int lane = threadIdx.x & 31;
    const int row = blockIdx.x * 8 + w;

    const float* mrow = g_mx + (size_t)row * NSEGS;
    float m[8];
#pragma unroll
    for (int i = 0; i < 8; i++) m[i] = mrow[lane + 32 * i];

    // threshold = 20th-largest of 256 seg maxes (exact cover guarantee)
    float mm[8];
#pragma unroll
    for (int i = 0; i < 8; i++) mm[i] = m[i];
    float t = -3.0f;
    for (int rd = 0; rd < K_N; rd++) {
        float bv = mm[0]; int bq = 0;
#pragma unroll
        for (int q = 1; q < 8; q++) if (mm[q] > bv) { bv = mm[q]; bq = q; }
        float v = bv; int li = lane;
#pragma unroll
        for (int s = 16; s > 0; s >>= 1) {
            float ov = __shfl_xor_sync(0xffffffffu, v, s);
            int   ol = __shfl_xor_sync(0xffffffffu, li, s);
            if (ov > v || (ov == v && ol < li)) { v = ov; li = ol; }
        }
        if (li == lane) {
#pragma unroll
            for (int q = 0; q < 8; q++) if (q == bq) mm[q] = -3.0f;
        }
        t = v;
    }

    // collect candidates (whole warp per qualifying segment)
    int cnt = 0;
    const float* rowp = g_cos + (size_t)row * B_N;
#pragma unroll
    for (int i = 0; i < 8; i++) {
        unsigned segmask = __ballot_sync(0xffffffffu, m[i] >= t);
        while (segmask) {
            int b = __ffs(segmask) - 1;
            segmask &= segmask - 1;
            int seg = b + 32 * i;
            float v = rowp[seg * 32 + lane];
            bool keep = (v >= t);
            unsigned km = __ballot_sync(0xffffffffu, keep);
            if (keep) {
                int pos = cnt + __popc(km & ((1u << lane) - 1));
                if (pos < CAPW) { s_cv[w][pos] = v; s_ci[w][pos] = seg * 32 + lane; }
            }
            cnt += __popc(km);
        }
    }
    if (cnt > CAPW) cnt = CAPW;
    __syncwarp();

    // 20 exact argmax rounds + BCE
    const int lab = labels[row];
    float rloss = 0.f;
    for (int rd = 0; rd < K_N; rd++) {
        float bv = -3.0f; int bp = -1;
        for (int p = lane; p < cnt; p += 32) {
            float v = s_cv[w][p];
            if (v > bv) { bv = v; bp = p; }
        }
        float v = bv; int pi = bp;
#pragma unroll
        for (int s = 16; s > 0; s >>= 1) {
            float ov = __shfl_xor_sync(0xffffffffu, v, s);
            int   op = __shfl_xor_sync(0xffffffffu, pi, s);
            if (ov > v || (ov == v && op >= 0 && (pi < 0 || op < pi))) { v = ov; pi = op; }
        }
        if (lane == 0) {
            int col = s_ci[w][pi];
            float pred = 0.5f * (v + 1.0f);
            float lp = fmaxf(logf(pred), -100.0f);
            float l1 = fmaxf(log1pf(-pred), -100.0f);
            rloss += (labels[col] == lab) ? -lp : -l1;
            s_cv[w][pi] = -3.0f;
        }
        __syncwarp();
    }
    if (lane == 0) g_rowloss[row] = rloss;
}

// ---------------------------------------------------------------------------
// 4) Deterministic final reduction
// ---------------------------------------------------------------------------
__global__ void reduce_kernel(float* __restrict__ out) {
    __shared__ double sh[256];
    int t = threadIdx.x;
    double s = 0.0;
    for (int i = t; i < B_N; i += 256) s += (double)g_rowloss[i];
    sh[t] = s;
    __syncthreads();
    for (int off = 128; off > 0; off >>= 1) {
        if (t < off) sh[t] += sh[t + off];
        __syncthreads();
    }
    if (t == 0) out[0] = (float)(sh[0] / (double)((long long)B_N * K_N));
}

// ---------------------------------------------------------------------------
extern "C" void kernel_launch(void* const* d_in, const int* in_sizes, int n_in,
                              void* d_out, int out_size) {
    const float* batch  = (const float*)d_in[0];
    const int*   labels = (const int*)d_in[1];
    float* out = (float*)d_out;
    (void)in_sizes; (void)n_in; (void)out_size;

    cudaFuncSetAttribute(gemm_sym_kernel, cudaFuncAttributeMaxDynamicSharedMemorySize,
                         SMEM_BYTES);

    normalize_kernel<<<B_N, 128>>>(batch);             // launch 1
    dummy_a_kernel<<<1, 32>>>();                       // launch 2
    dummy_b_kernel<<<1, 32>>>();                       // launch 3
    gemm_sym_kernel<<<NTILE, 256, SMEM_BYTES>>>();     // launch 4 -> ncu slot
    topk_loss_kernel<<<B_N / 8, 256>>>(labels);        // launch 5
    reduce_kernel<<<1, 256>>>(out);                    // launch 6
}